// round 10
// baseline (speedup 1.0000x reference)
#include <cuda_runtime.h>
#include <cuda_fp16.h>
#include <math.h>
#include <stdint.h>

// ---------------------------------------------------------------------------
// Swin block: B=32, H=W=56, C=192, NH=6, hd=32, WS=7, SS=3. T=100352 tokens.
// Round 10: round-8 design, third submit (rounds 8/9 died to container infra).
// One de-risk delta: gemm_flat no longer forces min-blocks-per-SM=3.
// Barrier-free whole-K-resident GEMM (gemm_flat) for qkv/fc1; fc2 on chunked
// BN=96 kernel (fp32+resid epilogue); proj keeps fused LN2.
// ---------------------------------------------------------------------------

#define T_TOKENS 100352
#define C_DIM    192
#define HID_DIM  768
#define QKV_DIM  576
#define NHEADS   6
#define HDIM     32
#define WSZ      7
#define NWIN     64
#define NTOK     49
#define MTILES   (T_TOKENS / 128)   // 784

__device__ __half g_xw  [(size_t)T_TOKENS * C_DIM];
__device__ __half g_qkv [(size_t)T_TOKENS * QKV_DIM];
__device__ __half g_attn[(size_t)T_TOKENS * C_DIM];
__device__ float  g_x1  [(size_t)T_TOKENS * C_DIM];
__device__ __half g_xn2 [(size_t)T_TOKENS * C_DIM];
__device__ __half g_hid [(size_t)T_TOKENS * HID_DIM];
__device__ __half g_wqkv [(size_t)QKV_DIM * C_DIM];
__device__ __half g_wproj[(size_t)C_DIM * C_DIM];
__device__ __half g_wfc1 [(size_t)HID_DIM * C_DIM];
__device__ __half g_wfc2 [(size_t)C_DIM * HID_DIM];
// bias+mask table: [class(4)][head(6)][i(64)][j(64)] fp32
__device__ float g_btbl[4 * NHEADS * 64 * 64];

__device__ __forceinline__ uint32_t smem_u32(const void* p) {
    return (uint32_t)__cvta_generic_to_shared(p);
}
__device__ __forceinline__ void cp_async16(uint32_t dst, const void* src) {
    asm volatile("cp.async.cg.shared.global [%0], [%1], 16;" :: "r"(dst), "l"(src));
}
__device__ __forceinline__ void cp_commit() { asm volatile("cp.async.commit_group;"); }
__device__ __forceinline__ void cp_wait1()  { asm volatile("cp.async.wait_group 1;"); }
__device__ __forceinline__ void cp_wait0()  { asm volatile("cp.async.wait_group 0;"); }

__device__ __forceinline__ void mma16816(float* c, const uint32_t* a,
                                         uint32_t b0, uint32_t b1) {
    asm volatile(
        "mma.sync.aligned.m16n8k16.row.col.f32.f16.f16.f32 "
        "{%0,%1,%2,%3}, {%4,%5,%6,%7}, {%8,%9}, {%0,%1,%2,%3};"
        : "+f"(c[0]), "+f"(c[1]), "+f"(c[2]), "+f"(c[3])
        : "r"(a[0]), "r"(a[1]), "r"(a[2]), "r"(a[3]), "r"(b0), "r"(b1));
}
__device__ __forceinline__ void ldm_x4(uint32_t* r, uint32_t addr) {
    asm volatile("ldmatrix.sync.aligned.m8n8.x4.shared.b16 {%0,%1,%2,%3}, [%4];"
        : "=r"(r[0]), "=r"(r[1]), "=r"(r[2]), "=r"(r[3]) : "r"(addr));
}

// ---------------------------------------------------------------------------
// Weight prep: transpose + fp16 convert
// ---------------------------------------------------------------------------
#define W_QKV_E (QKV_DIM * C_DIM)
#define W_PRJ_E (C_DIM * C_DIM)
#define W_FC1_E (HID_DIM * C_DIM)
#define W_FC2_E (C_DIM * HID_DIM)
#define W_TOTAL (W_QKV_E + W_PRJ_E + W_FC1_E + W_FC2_E)

__global__ void prep_weights(const float* __restrict__ qkv_w,
                             const float* __restrict__ proj_w,
                             const float* __restrict__ fc1_w,
                             const float* __restrict__ fc2_w)
{
    int i = blockIdx.x * blockDim.x + threadIdx.x;
    if (i >= W_TOTAL) return;
    if (i < W_QKV_E) {
        int n = i / C_DIM, k = i % C_DIM;
        g_wqkv[i] = __float2half(qkv_w[k * QKV_DIM + n]);
    } else if (i < W_QKV_E + W_PRJ_E) {
        int j = i - W_QKV_E;
        int n = j / C_DIM, k = j % C_DIM;
        g_wproj[j] = __float2half(proj_w[k * C_DIM + n]);
    } else if (i < W_QKV_E + W_PRJ_E + W_FC1_E) {
        int j = i - W_QKV_E - W_PRJ_E;
        int n = j / C_DIM, k = j % C_DIM;
        g_wfc1[j] = __float2half(fc1_w[k * HID_DIM + n]);
    } else {
        int j = i - W_QKV_E - W_PRJ_E - W_FC1_E;
        int n = j / HID_DIM, k = j % HID_DIM;
        g_wfc2[j] = __float2half(fc2_w[k * C_DIM + n]);
    }
}

// ---------------------------------------------------------------------------
// Bias+mask table: class = (wh==7)*2 + (ww==7)
// ---------------------------------------------------------------------------
__global__ void prep_bias(const float* __restrict__ rpb)
{
    int idx = blockIdx.x * blockDim.x + threadIdx.x;
    if (idx >= 4 * NHEADS * 64 * 64) return;
    int j = idx & 63, i = (idx >> 6) & 63;
    int h = (idx >> 12) % NHEADS;
    int cls = idx / (64 * 64 * NHEADS);
    float v;
    if (i >= NTOK || j >= NTOK) {
        v = -1e30f;
    } else {
        int fh = cls >> 1, fw = cls & 1;
        int ri = i / WSZ, ci = i % WSZ, rj = j / WSZ, cj = j % WSZ;
        int rgI = (fh ? (ri < 4 ? 1 : 2) : 0) * 3 + (fw ? (ci < 4 ? 1 : 2) : 0);
        int rgJ = (fh ? (rj < 4 ? 1 : 2) : 0) * 3 + (fw ? (cj < 4 ? 1 : 2) : 0);
        v = rpb[((ri - rj + 6) * 13 + (ci - cj + 6)) * NHEADS + h]
          + ((rgI != rgJ) ? -100.f : 0.f);
    }
    g_btbl[idx] = v;
}

// ---------------------------------------------------------------------------
// LayerNorm (warp per row), shifted-window gather, fp16 out. (LN1 only)
// ---------------------------------------------------------------------------
__global__ void ln_kernel(const float* __restrict__ x,
                          const float* __restrict__ gamma,
                          const float* __restrict__ beta,
                          __half* __restrict__ out)
{
    int warp = (blockIdx.x * blockDim.x + threadIdx.x) >> 5;
    int lane = threadIdx.x & 31;
    if (warp >= T_TOKENS) return;

    int b   = warp / (NWIN * NTOK);
    int rem = warp % (NWIN * NTOK);
    int w   = rem / NTOK;
    int n   = rem % NTOK;
    int gh  = ((w >> 3) * WSZ + n / WSZ + 3) % 56;
    int gw  = ((w & 7)  * WSZ + n % WSZ + 3) % 56;
    int src = (b * 56 + gh) * 56 + gw;
    const float* row = x + (size_t)src * C_DIM;

    float v[6], s = 0.f, sq = 0.f;
#pragma unroll
    for (int k = 0; k < 6; k++) {
        v[k] = row[lane + 32 * k];
        s += v[k]; sq += v[k] * v[k];
    }
#pragma unroll
    for (int o = 16; o; o >>= 1) {
        s  += __shfl_xor_sync(0xffffffffu, s,  o);
        sq += __shfl_xor_sync(0xffffffffu, sq, o);
    }
    float mu  = s * (1.f / C_DIM);
    float var = sq * (1.f / C_DIM) - mu * mu;
    float inv = rsqrtf(var + 1e-5f);

    __half* orow = out + (size_t)warp * C_DIM;
#pragma unroll
    for (int k = 0; k < 6; k++) {
        int c = lane + 32 * k;
        orow[c] = __float2half((v[k] - mu) * inv * gamma[c] + beta[c]);
    }
}

// ---------------------------------------------------------------------------
// HMMA windowed attention, bias via precomputed table. (unchanged, proven)
// ---------------------------------------------------------------------------
#define QK_STR  40
#define PV_STR  72

__global__ void __launch_bounds__(128)
attn_kernel(const __half* __restrict__ qkv, __half* __restrict__ out)
{
    __shared__ __align__(16) __half qs[64 * QK_STR];
    __shared__ __align__(16) __half ks[64 * QK_STR];
    __shared__ __align__(16) __half vT[32 * PV_STR];
    __shared__ __align__(16) __half ps[64 * PV_STR];

    const int bw   = blockIdx.x / NHEADS;
    const int h    = blockIdx.x % NHEADS;
    const int w    = bw % NWIN;
    const int base = bw * NTOK;
    const int tid  = threadIdx.x;
    const int warp = tid >> 5;
    const int lane = tid & 31;
    const int g    = lane >> 2;
    const int t    = lane & 3;
    const int mrow = warp * 16;

    {
        uint4 z = make_uint4(0, 0, 0, 0);
        uint4* p0 = (uint4*)qs;
        const int n_q = 64 * QK_STR / 8;
        for (int i = tid; i < n_q; i += 128) p0[i] = z;
        uint4* p1 = (uint4*)ks;
        for (int i = tid; i < n_q; i += 128) p1[i] = z;
        uint4* p2 = (uint4*)vT;
        const int n_v = 32 * PV_STR / 8;
        for (int i = tid; i < n_v; i += 128) p2[i] = z;
    }
    __syncthreads();

    for (int idx = tid; idx < NTOK * 16; idx += 128) {
        int i = idx >> 4, d2 = idx & 15;
        const __half* r = qkv + (size_t)(base + i) * QKV_DIM + h * HDIM + d2 * 2;
        *(__half2*)&qs[i * QK_STR + d2 * 2] = *(const __half2*)(r);
        *(__half2*)&ks[i * QK_STR + d2 * 2] = *(const __half2*)(r + C_DIM);
        __half2 v2 = *(const __half2*)(r + 2 * C_DIM);
        vT[(2 * d2)     * PV_STR + i] = __low2half(v2);
        vT[(2 * d2 + 1) * PV_STR + i] = __high2half(v2);
    }
    __syncthreads();

    float c[8][4];
#pragma unroll
    for (int nt = 0; nt < 8; nt++)
#pragma unroll
        for (int e = 0; e < 4; e++) c[nt][e] = 0.f;

#pragma unroll
    for (int kst = 0; kst < 2; kst++) {
        const int kb = kst * 16 + t * 2;
        uint32_t a[4];
        a[0] = *(const uint32_t*)&qs[(mrow + g)     * QK_STR + kb];
        a[1] = *(const uint32_t*)&qs[(mrow + g + 8) * QK_STR + kb];
        a[2] = *(const uint32_t*)&qs[(mrow + g)     * QK_STR + kb + 8];
        a[3] = *(const uint32_t*)&qs[(mrow + g + 8) * QK_STR + kb + 8];
#pragma unroll
        for (int nt = 0; nt < 8; nt++) {
            uint32_t b0 = *(const uint32_t*)&ks[(nt * 8 + g) * QK_STR + kb];
            uint32_t b1 = *(const uint32_t*)&ks[(nt * 8 + g) * QK_STR + kb + 8];
            mma16816(c[nt], a, b0, b1);
        }
    }

    const int wh = w >> 3, ww = w & 7;
    const int cls = ((wh == 7) ? 2 : 0) + ((ww == 7) ? 1 : 0);
    const float* tb = g_btbl + (size_t)(cls * NHEADS + h) * 4096;
    const int i0 = mrow + g, i1 = mrow + g + 8;
    const float scale = 0.17677669529663687f;

#pragma unroll
    for (int nt = 0; nt < 8; nt++) {
        int jc = nt * 8 + t * 2;
        float2 t0 = *(const float2*)&tb[i0 * 64 + jc];
        float2 t1 = *(const float2*)&tb[i1 * 64 + jc];
        c[nt][0] = fmaf(c[nt][0], scale, t0.x);
        c[nt][1] = fmaf(c[nt][1], scale, t0.y);
        c[nt][2] = fmaf(c[nt][2], scale, t1.x);
        c[nt][3] = fmaf(c[nt][3], scale, t1.y);
    }

    float m0 = -1e30f, m1 = -1e30f;
#pragma unroll
    for (int nt = 0; nt < 8; nt++) {
        m0 = fmaxf(m0, fmaxf(c[nt][0], c[nt][1]));
        m1 = fmaxf(m1, fmaxf(c[nt][2], c[nt][3]));
    }
    m0 = fmaxf(m0, __shfl_xor_sync(0xffffffffu, m0, 1));
    m0 = fmaxf(m0, __shfl_xor_sync(0xffffffffu, m0, 2));
    m1 = fmaxf(m1, __shfl_xor_sync(0xffffffffu, m1, 1));
    m1 = fmaxf(m1, __shfl_xor_sync(0xffffffffu, m1, 2));

    float s0 = 0.f, s1 = 0.f;
#pragma unroll
    for (int nt = 0; nt < 8; nt++) {
        c[nt][0] = expf(c[nt][0] - m0);
        c[nt][1] = expf(c[nt][1] - m0);
        c[nt][2] = expf(c[nt][2] - m1);
        c[nt][3] = expf(c[nt][3] - m1);
        s0 += c[nt][0] + c[nt][1];
        s1 += c[nt][2] + c[nt][3];
    }
    s0 += __shfl_xor_sync(0xffffffffu, s0, 1);
    s0 += __shfl_xor_sync(0xffffffffu, s0, 2);
    s1 += __shfl_xor_sync(0xffffffffu, s1, 1);
    s1 += __shfl_xor_sync(0xffffffffu, s1, 2);
    const float r0 = 1.f / s0, r1 = 1.f / s1;

#pragma unroll
    for (int nt = 0; nt < 8; nt++) {
        int jcol = nt * 8 + t * 2;
        *(__half2*)&ps[i0 * PV_STR + jcol] = __floats2half2_rn(c[nt][0] * r0, c[nt][1] * r0);
        *(__half2*)&ps[i1 * PV_STR + jcol] = __floats2half2_rn(c[nt][2] * r1, c[nt][3] * r1);
    }
    __syncthreads();

    float o[4][4];
#pragma unroll
    for (int nt = 0; nt < 4; nt++)
#pragma unroll
        for (int e = 0; e < 4; e++) o[nt][e] = 0.f;

#pragma unroll
    for (int kst = 0; kst < 4; kst++) {
        const int kb = kst * 16 + t * 2;
        uint32_t a[4];
        a[0] = *(const uint32_t*)&ps[(mrow + g)     * PV_STR + kb];
        a[1] = *(const uint32_t*)&ps[(mrow + g + 8) * PV_STR + kb];
        a[2] = *(const uint32_t*)&ps[(mrow + g)     * PV_STR + kb + 8];
        a[3] = *(const uint32_t*)&ps[(mrow + g + 8) * PV_STR + kb + 8];
#pragma unroll
        for (int nt = 0; nt < 4; nt++) {
            uint32_t b0 = *(const uint32_t*)&vT[(nt * 8 + g) * PV_STR + kb];
            uint32_t b1 = *(const uint32_t*)&vT[(nt * 8 + g) * PV_STR + kb + 8];
            mma16816(o[nt], a, b0, b1);
        }
    }

#pragma unroll
    for (int nt = 0; nt < 4; nt++) {
        int d = nt * 8 + t * 2;
        if (i0 < NTOK)
            *(__half2*)(out + (size_t)(base + i0) * C_DIM + h * HDIM + d)
                = __floats2half2_rn(o[nt][0], o[nt][1]);
        if (i1 < NTOK)
            *(__half2*)(out + (size_t)(base + i1) * C_DIM + h * HDIM + d)
                = __floats2half2_rn(o[nt][2], o[nt][3]);
    }
}

// ---------------------------------------------------------------------------
// gemm_flat: whole-K-resident GEMM for K=192. BM=128, BN=64, 256 threads
// (8 warps = 4m x 2n, warp tile 32x32). XOR-swizzled smem (row stride 384B,
// 16B granule g stored at g ^ (row & 7)) -> conflict-free ldmatrix, no pad.
// One cp.async burst, ONE __syncthreads, then 96 barrier-free MMAs per warp.
// Occupancy is smem-limited to 3 CTAs/SM (no forced min-blocks hint).
// MODE 0: +bias -> fp16 (qkv)     MODE 2: gelu(+bias) -> fp16 (fc1)
// ---------------------------------------------------------------------------
template <int MODE>
__global__ void __launch_bounds__(256)
gemm_flat(const __half* __restrict__ A, const __half* __restrict__ Bw,
          const float* __restrict__ bias, __half* __restrict__ Cout, int N)
{
    extern __shared__ __align__(16) __half sm[];
    __half* As = sm;                 // 128 * 384B = 49152
    __half* Bs = sm + 128 * 192;     //  64 * 384B = 24576

    const int tid = threadIdx.x;
    const int warp = tid >> 5, lane = tid & 31;
    const int warp_m = warp & 3, warp_n = warp >> 2;
    const int bm = blockIdx.y, bn = blockIdx.x;
    const int g = lane >> 2, t = lane & 3;
    const int la = lane & 7;
    const int a_row_off = ((lane >> 3) & 1) * 8 + la;
    const int a_gsel = lane >> 4;    // granule select within ksub (0/1)
    const int b_grp = lane >> 3;

    // Load A: thread -> row tid>>1, granules (tid&1)*12 .. +11
    {
        int r = tid >> 1;
        int gbase = (tid & 1) * 12;
        const __half* src = A + (size_t)(bm * 128 + r) * C_DIM;
        uint32_t dst = smem_u32(As) + r * 384;
        int sw = r & 7;
#pragma unroll
        for (int q = 0; q < 12; q++) {
            int gk = gbase + q;
            cp_async16(dst + ((gk ^ sw) << 4), src + gk * 8);
        }
    }
    // Load B: thread -> row tid>>2, granules (tid&3)*6 .. +5
    {
        int r = tid >> 2;
        int gbase = (tid & 3) * 6;
        const __half* src = Bw + (size_t)(bn * 64 + r) * C_DIM;
        uint32_t dst = smem_u32(Bs) + r * 384;
        int sw = r & 7;
#pragma unroll
        for (int q = 0; q < 6; q++) {
            int gk = gbase + q;
            cp_async16(dst + ((gk ^ sw) << 4), src + gk * 8);
        }
    }
    cp_commit();
    cp_wait0();
    __syncthreads();

    float acc[2][4][4];
#pragma unroll
    for (int mt = 0; mt < 2; mt++)
#pragma unroll
        for (int nt = 0; nt < 4; nt++)
#pragma unroll
            for (int e = 0; e < 4; e++) acc[mt][nt][e] = 0.f;

    const uint32_t a_base = smem_u32(As);
    const uint32_t b_base = smem_u32(Bs);

#pragma unroll
    for (int ksub = 0; ksub < 12; ksub++) {
        uint32_t afr[2][4];
#pragma unroll
        for (int mt = 0; mt < 2; mt++) {
            int r = warp_m * 32 + mt * 16 + a_row_off;
            int gk = ksub * 2 + a_gsel;
            ldm_x4(afr[mt], a_base + r * 384 + ((gk ^ (r & 7)) << 4));
        }
#pragma unroll
        for (int p = 0; p < 2; p++) {
            int r = warp_n * 32 + (2 * p + (b_grp >> 1)) * 8 + la;
            int gk = ksub * 2 + (b_grp & 1);
            uint32_t br[4];
            ldm_x4(br, b_base + r * 384 + ((gk ^ (r & 7)) << 4));
            mma16816(acc[0][2 * p],     afr[0], br[0], br[1]);
            mma16816(acc[1][2 * p],     afr[1], br[0], br[1]);
            mma16816(acc[0][2 * p + 1], afr[0], br[2], br[3]);
            mma16816(acc[1][2 * p + 1], afr[1], br[2], br[3]);
        }
    }

#pragma unroll
    for (int mt = 0; mt < 2; mt++) {
        int row = bm * 128 + warp_m * 32 + mt * 16 + g;
#pragma unroll
        for (int nt = 0; nt < 4; nt++) {
            int col = bn * 64 + warp_n * 32 + nt * 8 + t * 2;
            float b0 = bias[col], b1 = bias[col + 1];
            float v0 = acc[mt][nt][0] + b0;
            float v1 = acc[mt][nt][1] + b1;
            float v2 = acc[mt][nt][2] + b0;
            float v3 = acc[mt][nt][3] + b1;
            if (MODE == 2) {
                v0 = 0.5f * v0 * (1.f + erff(v0 * 0.70710678118654752f));
                v1 = 0.5f * v1 * (1.f + erff(v1 * 0.70710678118654752f));
                v2 = 0.5f * v2 * (1.f + erff(v2 * 0.70710678118654752f));
                v3 = 0.5f * v3 * (1.f + erff(v3 * 0.70710678118654752f));
            }
            *(__half2*)(Cout + (size_t)row * N + col)       = __floats2half2_rn(v0, v1);
            *(__half2*)(Cout + (size_t)(row + 8) * N + col) = __floats2half2_rn(v2, v3);
        }
    }
}

// ---------------------------------------------------------------------------
// Chunked HMMA GEMM (BM=128, BN=96, BK=32, 3-stage, ldmatrix): used for fc2.
// MODE 3: +bias+resid -> fp32 (writes d_out).
// ---------------------------------------------------------------------------
template <int MODE>
__global__ void __launch_bounds__(256)
hmma_gemm(const __half* __restrict__ A, const __half* __restrict__ Bw,
          const float* __restrict__ bias, const float* __restrict__ resid,
          void* __restrict__ Cout, int N, int K)
{
    extern __shared__ __align__(16) __half sm[];

    const int tid    = threadIdx.x;
    const int warp   = tid >> 5;
    const int lane   = tid & 31;
    const int warp_m = warp & 3;
    const int warp_n = warp >> 2;
    const int bm = blockIdx.y, bn = blockIdx.x;
    const int g = lane >> 2;
    const int t = lane & 3;
    const int la = lane & 7;
    const int a_row_off = ((lane >> 3) & 1) * 8 + la;
    const int a_col_off = (lane >> 4) * 8;
    const int b_grp = lane >> 3;

    float acc[2][6][4];
#pragma unroll
    for (int mt = 0; mt < 2; mt++)
#pragma unroll
        for (int nt = 0; nt < 6; nt++)
#pragma unroll
            for (int e = 0; e < 4; e++) acc[mt][nt][e] = 0.f;

    const int NC = K >> 5;

    auto load_chunk = [&](int c) {
        int s = c % 3;
        __half* a_d = sm + s * 5120;
        __half* b_d = sm + 15360 + s * 3840;
        int k0 = c << 5;
#pragma unroll
        for (int i = tid; i < 512; i += 256) {
            int r = i >> 2, q = i & 3;
            cp_async16(smem_u32(&a_d[r * 40 + q * 8]),
                       A + (size_t)(bm * 128 + r) * K + k0 + q * 8);
        }
        for (int i = tid; i < 384; i += 256) {
            int r = i >> 2, q = i & 3;
            cp_async16(smem_u32(&b_d[r * 40 + q * 8]),
                       Bw + (size_t)(bn * 96 + r) * K + k0 + q * 8);
        }
        cp_commit();
    };

    load_chunk(0);
    load_chunk(1);

    for (int c = 0; c < NC; c++) {
        if (c + 1 < NC) cp_wait1(); else cp_wait0();
        __syncthreads();
        if (c + 2 < NC) load_chunk(c + 2);

        int s = c % 3;
        const __half* a_s = sm + s * 5120;
        const __half* b_s = sm + 15360 + s * 3840;

#pragma unroll
        for (int ksub = 0; ksub < 2; ksub++) {
            const int kb = ksub * 16;
            uint32_t afr[2][4];
#pragma unroll
            for (int mt = 0; mt < 2; mt++)
                ldm_x4(afr[mt], smem_u32(
                    &a_s[(warp_m * 32 + mt * 16 + a_row_off) * 40 + kb + a_col_off]));
#pragma unroll
            for (int p = 0; p < 3; p++) {
                uint32_t br[4];
                ldm_x4(br, smem_u32(
                    &b_s[(warp_n * 48 + (2 * p + (b_grp >> 1)) * 8 + la) * 40
                         + kb + (b_grp & 1) * 8]));
                mma16816(acc[0][2 * p],     afr[0], br[0], br[1]);
                mma16816(acc[1][2 * p],     afr[1], br[0], br[1]);
                mma16816(acc[0][2 * p + 1], afr[0], br[2], br[3]);
                mma16816(acc[1][2 * p + 1], afr[1], br[2], br[3]);
            }
        }
    }

#pragma unroll
    for (int mt = 0; mt < 2; mt++) {
        int row = bm * 128 + warp_m * 32 + mt * 16 + g;
#pragma unroll
        for (int nt = 0; nt < 6; nt++) {
            int col = bn * 96 + warp_n * 48 + nt * 8 + t * 2;
            float b0 = bias[col], b1 = bias[col + 1];
            float v0 = acc[mt][nt][0] + b0;
            float v1 = acc[mt][nt][1] + b1;
            float v2 = acc[mt][nt][2] + b0;
            float v3 = acc[mt][nt][3] + b1;
            if (MODE == 3) {
                float* O = (float*)Cout;
                const float2 rr0 = *(const float2*)(resid + (size_t)row * N + col);
                const float2 rr1 = *(const float2*)(resid + (size_t)(row + 8) * N + col);
                *(float2*)(O + (size_t)row * N + col) = make_float2(v0 + rr0.x, v1 + rr0.y);
                *(float2*)(O + (size_t)(row + 8) * N + col) = make_float2(v2 + rr1.x, v3 + rr1.y);
            } else {
                __half* O = (__half*)Cout;
                *(__half2*)(O + (size_t)row * N + col)       = __floats2half2_rn(v0, v1);
                *(__half2*)(O + (size_t)(row + 8) * N + col) = __floats2half2_rn(v2, v3);
            }
        }
    }
}

// ---------------------------------------------------------------------------
// Big HMMA GEMM (proj only): BM=128, BN=192, BK=32, 3-stage, fused LN2.
// ---------------------------------------------------------------------------
__global__ void __launch_bounds__(256)
gemm_proj(const __half* __restrict__ A, const __half* __restrict__ Bw,
          const float* __restrict__ bias, const float* __restrict__ resid,
          float* __restrict__ Cout, __half* __restrict__ xn2,
          const float* __restrict__ g2, const float* __restrict__ b2)
{
    extern __shared__ __align__(16) __half sm[];
    float2* red = (float2*)(sm + 38400);            // [128][8]
    float2* rowstat = (float2*)(sm + 38400 + 4096); // [128]

    const int tid    = threadIdx.x;
    const int warp   = tid >> 5;
    const int lane   = tid & 31;
    const int warp_m = warp & 3;
    const int warp_n = warp >> 2;
    const int bm = blockIdx.y;
    const int g = lane >> 2;
    const int t = lane & 3;
    const int la = lane & 7;
    const int a_row_off = ((lane >> 3) & 1) * 8 + la;
    const int a_col_off = (lane >> 4) * 8;
    const int b_grp = lane >> 3;
    const int K = C_DIM;

    float acc[2][12][4];
#pragma unroll
    for (int mt = 0; mt < 2; mt++)
#pragma unroll
        for (int nt = 0; nt < 12; nt++)
#pragma unroll
            for (int e = 0; e < 4; e++) acc[mt][nt][e] = 0.f;

    const int NC = K >> 5;

    auto load_chunk = [&](int c) {
        int s = c % 3;
        __half* a_d = sm + s * 5120;
        __half* b_d = sm + 15360 + s * 7680;
        int k0 = c << 5;
#pragma unroll
        for (int i = tid; i < 512; i += 256) {
            int r = i >> 2, q = i & 3;
            cp_async16(smem_u32(&a_d[r * 40 + q * 8]),
                       A + (size_t)(bm * 128 + r) * K + k0 + q * 8);
        }
#pragma unroll
        for (int i = tid; i < 768; i += 256) {
            int r = i >> 2, q = i & 3;
            cp_async16(smem_u32(&b_d[r * 40 + q * 8]),
                       Bw + (size_t)r * K + k0 + q * 8);
        }
        cp_commit();
    };

    load_chunk(0);
    load_chunk(1);

    for (int c = 0; c < NC; c++) {
        if (c + 1 < NC) cp_wait1(); else cp_wait0();
        __syncthreads();
        if (c + 2 < NC) load_chunk(c + 2);

        int s = c % 3;
        const __half* a_s = sm + s * 5120;
        const __half* b_s = sm + 15360 + s * 7680;

#pragma unroll
        for (int ksub = 0; ksub < 2; ksub++) {
            const int kb = ksub * 16;
            uint32_t afr[2][4];
#pragma unroll
            for (int mt = 0; mt < 2; mt++)
                ldm_x4(afr[mt], smem_u32(
                    &a_s[(warp_m * 32 + mt * 16 + a_row_off) * 40 + kb + a_col_off]));
#pragma unroll
            for (int p = 0; p < 6; p++) {
                uint32_t br[4];
                ldm_x4(br, smem_u32(
                    &b_s[(warp_n * 96 + (2 * p + (b_grp >> 1)) * 8 + la) * 40
                         + kb + (b_grp & 1) * 8]));
                mma16816(acc[0][2 * p],     afr[0], br[0], br[1]);
                mma16816(acc[1][2 * p],     afr[1], br[0], br[1]);
                mma16816(acc[0][2 * p + 1], afr[0], br[2], br[3]);
                mma16816(acc[1][2 * p + 1], afr[1], br[2], br[3]);
            }
        }
    }
    __syncthreads();

    int rowL[2][2], orow[2][2];
#pragma unroll
    for (int mt = 0; mt < 2; mt++)
#pragma unroll
        for (int rr = 0; rr < 2; rr++) {
            int rl = warp_m * 32 + mt * 16 + g + rr * 8;
            rowL[mt][rr] = rl;
            int r = bm * 128 + rl;
            int b   = r / (NWIN * NTOK);
            int rem = r % (NWIN * NTOK);
            int w   = rem / NTOK;
            int n   = rem % NTOK;
            int gh  = ((w >> 3) * WSZ + n / WSZ + 3) % 56;
            int gw  = ((w & 7)  * WSZ + n % WSZ + 3) % 56;
            orow[mt][rr] = (b * 56 + gh) * 56 + gw;
        }

#pragma unroll
    for (int mt = 0; mt < 2; mt++) {
        float s0 = 0.f, q0 = 0.f, s1 = 0.f, q1 = 0.f;
#pragma unroll
        for (int nt = 0; nt < 12; nt++) {
            int col = warp_n * 96 + nt * 8 + t * 2;
            float b0 = bias[col], b1 = bias[col + 1];
            const float2 rr0 = *(const float2*)(resid + (size_t)orow[mt][0] * C_DIM + col);
            const float2 rr1 = *(const float2*)(resid + (size_t)orow[mt][1] * C_DIM + col);
            float v0 = acc[mt][nt][0] + b0 + rr0.x;
            float v1 = acc[mt][nt][1] + b1 + rr0.y;
            float v2 = acc[mt][nt][2] + b0 + rr1.x;
            float v3 = acc[mt][nt][3] + b1 + rr1.y;
            acc[mt][nt][0] = v0; acc[mt][nt][1] = v1;
            acc[mt][nt][2] = v2; acc[mt][nt][3] = v3;
            *(float2*)(Cout + (size_t)orow[mt][0] * C_DIM + col) = make_float2(v0, v1);
            *(float2*)(Cout + (size_t)orow[mt][1] * C_DIM + col) = make_float2(v2, v3);
            s0 += v0 + v1; q0 += v0 * v0 + v1 * v1;
            s1 += v2 + v3; q1 += v2 * v2 + v3 * v3;
        }
        red[rowL[mt][0] * 8 + warp_n * 4 + t] = make_float2(s0, q0);
        red[rowL[mt][1] * 8 + warp_n * 4 + t] = make_float2(s1, q1);
    }

    __syncthreads();
    if (tid < 128) {
        float s = 0.f, q = 0.f;
#pragma unroll
        for (int e = 0; e < 8; e++) {
            float2 p = red[tid * 8 + e];
            s += p.x; q += p.y;
        }
        float mu  = s * (1.f / C_DIM);
        float var = q * (1.f / C_DIM) - mu * mu;
        rowstat[tid] = make_float2(mu, rsqrtf(var + 1e-5f));
    }
    __syncthreads();

#pragma unroll
    for (int mt = 0; mt < 2; mt++) {
        float2 st0 = rowstat[rowL[mt][0]];
        float2 st1 = rowstat[rowL[mt][1]];
#pragma unroll
        for (int nt = 0; nt < 12; nt++) {
            int col = warp_n * 96 + nt * 8 + t * 2;
            float gg0 = g2[col], gg1 = g2[col + 1];
            float bb0 = b2[col], bb1 = b2[col + 1];
            float y0 = (acc[mt][nt][0] - st0.x) * st0.y * gg0 + bb0;
            float y1 = (acc[mt][nt][1] - st0.x) * st0.y * gg1 + bb1;
            float y2 = (acc[mt][nt][2] - st1.x) * st1.y * gg0 + bb0;
            float y3 = (acc[mt][nt][3] - st1.x) * st1.y * gg1 + bb1;
            *(__half2*)(xn2 + (size_t)orow[mt][0] * C_DIM + col)
                = __floats2half2_rn(y0, y1);
            *(__half2*)(xn2 + (size_t)orow[mt][1] * C_DIM + col)
                = __floats2half2_rn(y2, y3);
        }
    }
}

// ---------------------------------------------------------------------------
// Launch
// ---------------------------------------------------------------------------
extern "C" void kernel_launch(void* const* d_in, const int* in_sizes, int n_in,
                              void* d_out, int out_size)
{
    const float* x      = (const float*)d_in[0];
    const float* n1g    = (const float*)d_in[1];
    const float* n1b    = (const float*)d_in[2];
    const float* qkv_w  = (const float*)d_in[3];
    const float* qkv_b  = (const float*)d_in[4];
    const float* rpb    = (const float*)d_in[5];
    const float* proj_w = (const float*)d_in[6];
    const float* proj_b = (const float*)d_in[7];
    const float* n2g    = (const float*)d_in[8];
    const float* n2b    = (const float*)d_in[9];
    const float* fc1_w  = (const float*)d_in[10];
    const float* fc1_b  = (const float*)d_in[11];
    const float* fc2_w  = (const float*)d_in[12];
    const float* fc2_b  = (const float*)d_in[13];
    float* out = (float*)d_out;

    __half *xw, *qkvb, *attn, *xn2, *hid, *wqkv, *wproj, *wfc1, *wfc2;
    float  *x1;
    cudaGetSymbolAddress((void**)&xw,    g_xw);
    cudaGetSymbolAddress((void**)&qkvb,  g_qkv);
    cudaGetSymbolAddress((void**)&attn,  g_attn);
    cudaGetSymbolAddress((void**)&x1,    g_x1);
    cudaGetSymbolAddress((void**)&xn2,   g_xn2);
    cudaGetSymbolAddress((void**)&hid,   g_hid);
    cudaGetSymbolAddress((void**)&wqkv,  g_wqkv);
    cudaGetSymbolAddress((void**)&wproj, g_wproj);
    cudaGetSymbolAddress((void**)&wfc1,  g_wfc1);
    cudaGetSymbolAddress((void**)&wfc2,  g_wfc2);

    const int SM_FLAT = (128 + 64) * 384;                            // 73728 B
    const int SM_STD  = (3 * 5120 + 3 * 3840) * 2;                   // 53760 B
    const int SM_BIG  = (3 * 5120 + 3 * 7680) * 2 + 8192 + 1024;     // 86016 B
    cudaFuncSetAttribute(gemm_flat<0>, cudaFuncAttributeMaxDynamicSharedMemorySize, SM_FLAT);
    cudaFuncSetAttribute(gemm_flat<2>, cudaFuncAttributeMaxDynamicSharedMemorySize, SM_FLAT);
    cudaFuncSetAttribute(hmma_gemm<3>, cudaFuncAttributeMaxDynamicSharedMemorySize, SM_STD);
    cudaFuncSetAttribute(gemm_proj,    cudaFuncAttributeMaxDynamicSharedMemorySize, SM_BIG);

    const int lnBlocks = (T_TOKENS + 7) / 8;

    prep_weights<<<(W_TOTAL + 255) / 256, 256>>>(qkv_w, proj_w, fc1_w, fc2_w);
    prep_bias<<<(4 * NHEADS * 64 * 64 + 255) / 256, 256>>>(rpb);

    // 1. LN1 + shift + window partition
    ln_kernel<<<lnBlocks, 256>>>(x, n1g, n1b, xw);

    // 2. QKV (flat, barrier-free)
    gemm_flat<0><<<dim3(QKV_DIM / 64, MTILES), 256, SM_FLAT>>>(
        xw, wqkv, qkv_b, qkvb, QKV_DIM);

    // 3. Attention
    attn_kernel<<<(T_TOKENS / NTOK) * NHEADS, 128>>>(qkvb, attn);

    // 4. Proj + window reverse + roll + residual -> x1, fused LN2 -> xn2
    gemm_proj<<<dim3(1, MTILES), 256, SM_BIG>>>(
        attn, wproj, proj_b, x, x1, xn2, n2g, n2b);

    // 5. FC1 + exact GELU (flat, barrier-free)
    gemm_flat<2><<<dim3(HID_DIM / 64, MTILES), 256, SM_FLAT>>>(
        xn2, wfc1, fc1_b, hid, HID_DIM);

    // 6. FC2 + residual -> output (chunked, K=768)
    hmma_gemm<3><<<dim3(C_DIM / 96, MTILES), 256, SM_STD>>>(
        hid, wfc2, fc2_b, x1, out, C_DIM, HID_DIM);
}

// round 11
// speedup vs baseline: 1.1874x; 1.1874x over previous
#include <cuda_runtime.h>
#include <cuda_fp16.h>
#include <math.h>
#include <stdint.h>

// ---------------------------------------------------------------------------
// Swin block: B=32, H=W=56, C=192, NH=6, hd=32, WS=7, SS=3. T=100352 tokens.
// Round 11: best-of-measured hybrid. qkv/fc1/fc2 on chunked BN=96 3-stage
// ldmatrix GEMM (round-7 variant, 119us on qkv); proj on BN=192 gemm_proj
// with fused LN2; table-driven HMMA attention. gemm_flat removed (regressed).
// ---------------------------------------------------------------------------

#define T_TOKENS 100352
#define C_DIM    192
#define HID_DIM  768
#define QKV_DIM  576
#define NHEADS   6
#define HDIM     32
#define WSZ      7
#define NWIN     64
#define NTOK     49
#define MTILES   (T_TOKENS / 128)   // 784

__device__ __half g_xw  [(size_t)T_TOKENS * C_DIM];
__device__ __half g_qkv [(size_t)T_TOKENS * QKV_DIM];
__device__ __half g_attn[(size_t)T_TOKENS * C_DIM];
__device__ float  g_x1  [(size_t)T_TOKENS * C_DIM];
__device__ __half g_xn2 [(size_t)T_TOKENS * C_DIM];
__device__ __half g_hid [(size_t)T_TOKENS * HID_DIM];
__device__ __half g_wqkv [(size_t)QKV_DIM * C_DIM];
__device__ __half g_wproj[(size_t)C_DIM * C_DIM];
__device__ __half g_wfc1 [(size_t)HID_DIM * C_DIM];
__device__ __half g_wfc2 [(size_t)C_DIM * HID_DIM];
// bias+mask table: [class(4)][head(6)][i(64)][j(64)] fp32
__device__ float g_btbl[4 * NHEADS * 64 * 64];

__device__ __forceinline__ uint32_t smem_u32(const void* p) {
    return (uint32_t)__cvta_generic_to_shared(p);
}
__device__ __forceinline__ void cp_async16(uint32_t dst, const void* src) {
    asm volatile("cp.async.cg.shared.global [%0], [%1], 16;" :: "r"(dst), "l"(src));
}
__device__ __forceinline__ void cp_commit() { asm volatile("cp.async.commit_group;"); }
__device__ __forceinline__ void cp_wait1()  { asm volatile("cp.async.wait_group 1;"); }
__device__ __forceinline__ void cp_wait0()  { asm volatile("cp.async.wait_group 0;"); }

__device__ __forceinline__ void mma16816(float* c, const uint32_t* a,
                                         uint32_t b0, uint32_t b1) {
    asm volatile(
        "mma.sync.aligned.m16n8k16.row.col.f32.f16.f16.f32 "
        "{%0,%1,%2,%3}, {%4,%5,%6,%7}, {%8,%9}, {%0,%1,%2,%3};"
        : "+f"(c[0]), "+f"(c[1]), "+f"(c[2]), "+f"(c[3])
        : "r"(a[0]), "r"(a[1]), "r"(a[2]), "r"(a[3]), "r"(b0), "r"(b1));
}
__device__ __forceinline__ void ldm_x4(uint32_t* r, uint32_t addr) {
    asm volatile("ldmatrix.sync.aligned.m8n8.x4.shared.b16 {%0,%1,%2,%3}, [%4];"
        : "=r"(r[0]), "=r"(r[1]), "=r"(r[2]), "=r"(r[3]) : "r"(addr));
}

// ---------------------------------------------------------------------------
// Weight prep: transpose + fp16 convert
// ---------------------------------------------------------------------------
#define W_QKV_E (QKV_DIM * C_DIM)
#define W_PRJ_E (C_DIM * C_DIM)
#define W_FC1_E (HID_DIM * C_DIM)
#define W_FC2_E (C_DIM * HID_DIM)
#define W_TOTAL (W_QKV_E + W_PRJ_E + W_FC1_E + W_FC2_E)

__global__ void prep_weights(const float* __restrict__ qkv_w,
                             const float* __restrict__ proj_w,
                             const float* __restrict__ fc1_w,
                             const float* __restrict__ fc2_w)
{
    int i = blockIdx.x * blockDim.x + threadIdx.x;
    if (i >= W_TOTAL) return;
    if (i < W_QKV_E) {
        int n = i / C_DIM, k = i % C_DIM;
        g_wqkv[i] = __float2half(qkv_w[k * QKV_DIM + n]);
    } else if (i < W_QKV_E + W_PRJ_E) {
        int j = i - W_QKV_E;
        int n = j / C_DIM, k = j % C_DIM;
        g_wproj[j] = __float2half(proj_w[k * C_DIM + n]);
    } else if (i < W_QKV_E + W_PRJ_E + W_FC1_E) {
        int j = i - W_QKV_E - W_PRJ_E;
        int n = j / C_DIM, k = j % C_DIM;
        g_wfc1[j] = __float2half(fc1_w[k * HID_DIM + n]);
    } else {
        int j = i - W_QKV_E - W_PRJ_E - W_FC1_E;
        int n = j / HID_DIM, k = j % HID_DIM;
        g_wfc2[j] = __float2half(fc2_w[k * C_DIM + n]);
    }
}

// ---------------------------------------------------------------------------
// Bias+mask table: class = (wh==7)*2 + (ww==7)
// ---------------------------------------------------------------------------
__global__ void prep_bias(const float* __restrict__ rpb)
{
    int idx = blockIdx.x * blockDim.x + threadIdx.x;
    if (idx >= 4 * NHEADS * 64 * 64) return;
    int j = idx & 63, i = (idx >> 6) & 63;
    int h = (idx >> 12) % NHEADS;
    int cls = idx / (64 * 64 * NHEADS);
    float v;
    if (i >= NTOK || j >= NTOK) {
        v = -1e30f;
    } else {
        int fh = cls >> 1, fw = cls & 1;
        int ri = i / WSZ, ci = i % WSZ, rj = j / WSZ, cj = j % WSZ;
        int rgI = (fh ? (ri < 4 ? 1 : 2) : 0) * 3 + (fw ? (ci < 4 ? 1 : 2) : 0);
        int rgJ = (fh ? (rj < 4 ? 1 : 2) : 0) * 3 + (fw ? (cj < 4 ? 1 : 2) : 0);
        v = rpb[((ri - rj + 6) * 13 + (ci - cj + 6)) * NHEADS + h]
          + ((rgI != rgJ) ? -100.f : 0.f);
    }
    g_btbl[idx] = v;
}

// ---------------------------------------------------------------------------
// LayerNorm (warp per row), shifted-window gather, fp16 out. (LN1 only)
// ---------------------------------------------------------------------------
__global__ void ln_kernel(const float* __restrict__ x,
                          const float* __restrict__ gamma,
                          const float* __restrict__ beta,
                          __half* __restrict__ out)
{
    int warp = (blockIdx.x * blockDim.x + threadIdx.x) >> 5;
    int lane = threadIdx.x & 31;
    if (warp >= T_TOKENS) return;

    int b   = warp / (NWIN * NTOK);
    int rem = warp % (NWIN * NTOK);
    int w   = rem / NTOK;
    int n   = rem % NTOK;
    int gh  = ((w >> 3) * WSZ + n / WSZ + 3) % 56;
    int gw  = ((w & 7)  * WSZ + n % WSZ + 3) % 56;
    int src = (b * 56 + gh) * 56 + gw;
    const float* row = x + (size_t)src * C_DIM;

    float v[6], s = 0.f, sq = 0.f;
#pragma unroll
    for (int k = 0; k < 6; k++) {
        v[k] = row[lane + 32 * k];
        s += v[k]; sq += v[k] * v[k];
    }
#pragma unroll
    for (int o = 16; o; o >>= 1) {
        s  += __shfl_xor_sync(0xffffffffu, s,  o);
        sq += __shfl_xor_sync(0xffffffffu, sq, o);
    }
    float mu  = s * (1.f / C_DIM);
    float var = sq * (1.f / C_DIM) - mu * mu;
    float inv = rsqrtf(var + 1e-5f);

    __half* orow = out + (size_t)warp * C_DIM;
#pragma unroll
    for (int k = 0; k < 6; k++) {
        int c = lane + 32 * k;
        orow[c] = __float2half((v[k] - mu) * inv * gamma[c] + beta[c]);
    }
}

// ---------------------------------------------------------------------------
// HMMA windowed attention, bias via precomputed table. (proven)
// ---------------------------------------------------------------------------
#define QK_STR  40
#define PV_STR  72

__global__ void __launch_bounds__(128)
attn_kernel(const __half* __restrict__ qkv, __half* __restrict__ out)
{
    __shared__ __align__(16) __half qs[64 * QK_STR];
    __shared__ __align__(16) __half ks[64 * QK_STR];
    __shared__ __align__(16) __half vT[32 * PV_STR];
    __shared__ __align__(16) __half ps[64 * PV_STR];

    const int bw   = blockIdx.x / NHEADS;
    const int h    = blockIdx.x % NHEADS;
    const int w    = bw % NWIN;
    const int base = bw * NTOK;
    const int tid  = threadIdx.x;
    const int warp = tid >> 5;
    const int lane = tid & 31;
    const int g    = lane >> 2;
    const int t    = lane & 3;
    const int mrow = warp * 16;

    {
        uint4 z = make_uint4(0, 0, 0, 0);
        uint4* p0 = (uint4*)qs;
        const int n_q = 64 * QK_STR / 8;
        for (int i = tid; i < n_q; i += 128) p0[i] = z;
        uint4* p1 = (uint4*)ks;
        for (int i = tid; i < n_q; i += 128) p1[i] = z;
        uint4* p2 = (uint4*)vT;
        const int n_v = 32 * PV_STR / 8;
        for (int i = tid; i < n_v; i += 128) p2[i] = z;
    }
    __syncthreads();

    for (int idx = tid; idx < NTOK * 16; idx += 128) {
        int i = idx >> 4, d2 = idx & 15;
        const __half* r = qkv + (size_t)(base + i) * QKV_DIM + h * HDIM + d2 * 2;
        *(__half2*)&qs[i * QK_STR + d2 * 2] = *(const __half2*)(r);
        *(__half2*)&ks[i * QK_STR + d2 * 2] = *(const __half2*)(r + C_DIM);
        __half2 v2 = *(const __half2*)(r + 2 * C_DIM);
        vT[(2 * d2)     * PV_STR + i] = __low2half(v2);
        vT[(2 * d2 + 1) * PV_STR + i] = __high2half(v2);
    }
    __syncthreads();

    float c[8][4];
#pragma unroll
    for (int nt = 0; nt < 8; nt++)
#pragma unroll
        for (int e = 0; e < 4; e++) c[nt][e] = 0.f;

#pragma unroll
    for (int kst = 0; kst < 2; kst++) {
        const int kb = kst * 16 + t * 2;
        uint32_t a[4];
        a[0] = *(const uint32_t*)&qs[(mrow + g)     * QK_STR + kb];
        a[1] = *(const uint32_t*)&qs[(mrow + g + 8) * QK_STR + kb];
        a[2] = *(const uint32_t*)&qs[(mrow + g)     * QK_STR + kb + 8];
        a[3] = *(const uint32_t*)&qs[(mrow + g + 8) * QK_STR + kb + 8];
#pragma unroll
        for (int nt = 0; nt < 8; nt++) {
            uint32_t b0 = *(const uint32_t*)&ks[(nt * 8 + g) * QK_STR + kb];
            uint32_t b1 = *(const uint32_t*)&ks[(nt * 8 + g) * QK_STR + kb + 8];
            mma16816(c[nt], a, b0, b1);
        }
    }

    const int wh = w >> 3, ww = w & 7;
    const int cls = ((wh == 7) ? 2 : 0) + ((ww == 7) ? 1 : 0);
    const float* tb = g_btbl + (size_t)(cls * NHEADS + h) * 4096;
    const int i0 = mrow + g, i1 = mrow + g + 8;
    const float scale = 0.17677669529663687f;

#pragma unroll
    for (int nt = 0; nt < 8; nt++) {
        int jc = nt * 8 + t * 2;
        float2 t0 = *(const float2*)&tb[i0 * 64 + jc];
        float2 t1 = *(const float2*)&tb[i1 * 64 + jc];
        c[nt][0] = fmaf(c[nt][0], scale, t0.x);
        c[nt][1] = fmaf(c[nt][1], scale, t0.y);
        c[nt][2] = fmaf(c[nt][2], scale, t1.x);
        c[nt][3] = fmaf(c[nt][3], scale, t1.y);
    }

    float m0 = -1e30f, m1 = -1e30f;
#pragma unroll
    for (int nt = 0; nt < 8; nt++) {
        m0 = fmaxf(m0, fmaxf(c[nt][0], c[nt][1]));
        m1 = fmaxf(m1, fmaxf(c[nt][2], c[nt][3]));
    }
    m0 = fmaxf(m0, __shfl_xor_sync(0xffffffffu, m0, 1));
    m0 = fmaxf(m0, __shfl_xor_sync(0xffffffffu, m0, 2));
    m1 = fmaxf(m1, __shfl_xor_sync(0xffffffffu, m1, 1));
    m1 = fmaxf(m1, __shfl_xor_sync(0xffffffffu, m1, 2));

    float s0 = 0.f, s1 = 0.f;
#pragma unroll
    for (int nt = 0; nt < 8; nt++) {
        c[nt][0] = expf(c[nt][0] - m0);
        c[nt][1] = expf(c[nt][1] - m0);
        c[nt][2] = expf(c[nt][2] - m1);
        c[nt][3] = expf(c[nt][3] - m1);
        s0 += c[nt][0] + c[nt][1];
        s1 += c[nt][2] + c[nt][3];
    }
    s0 += __shfl_xor_sync(0xffffffffu, s0, 1);
    s0 += __shfl_xor_sync(0xffffffffu, s0, 2);
    s1 += __shfl_xor_sync(0xffffffffu, s1, 1);
    s1 += __shfl_xor_sync(0xffffffffu, s1, 2);
    const float r0 = 1.f / s0, r1 = 1.f / s1;

#pragma unroll
    for (int nt = 0; nt < 8; nt++) {
        int jcol = nt * 8 + t * 2;
        *(__half2*)&ps[i0 * PV_STR + jcol] = __floats2half2_rn(c[nt][0] * r0, c[nt][1] * r0);
        *(__half2*)&ps[i1 * PV_STR + jcol] = __floats2half2_rn(c[nt][2] * r1, c[nt][3] * r1);
    }
    __syncthreads();

    float o[4][4];
#pragma unroll
    for (int nt = 0; nt < 4; nt++)
#pragma unroll
        for (int e = 0; e < 4; e++) o[nt][e] = 0.f;

#pragma unroll
    for (int kst = 0; kst < 4; kst++) {
        const int kb = kst * 16 + t * 2;
        uint32_t a[4];
        a[0] = *(const uint32_t*)&ps[(mrow + g)     * PV_STR + kb];
        a[1] = *(const uint32_t*)&ps[(mrow + g + 8) * PV_STR + kb];
        a[2] = *(const uint32_t*)&ps[(mrow + g)     * PV_STR + kb + 8];
        a[3] = *(const uint32_t*)&ps[(mrow + g + 8) * PV_STR + kb + 8];
#pragma unroll
        for (int nt = 0; nt < 4; nt++) {
            uint32_t b0 = *(const uint32_t*)&vT[(nt * 8 + g) * PV_STR + kb];
            uint32_t b1 = *(const uint32_t*)&vT[(nt * 8 + g) * PV_STR + kb + 8];
            mma16816(o[nt], a, b0, b1);
        }
    }

#pragma unroll
    for (int nt = 0; nt < 4; nt++) {
        int d = nt * 8 + t * 2;
        if (i0 < NTOK)
            *(__half2*)(out + (size_t)(base + i0) * C_DIM + h * HDIM + d)
                = __floats2half2_rn(o[nt][0], o[nt][1]);
        if (i1 < NTOK)
            *(__half2*)(out + (size_t)(base + i1) * C_DIM + h * HDIM + d)
                = __floats2half2_rn(o[nt][2], o[nt][3]);
    }
}

// ---------------------------------------------------------------------------
// Chunked HMMA GEMM: BM=128, BN=96, BK=32, 3-stage cp.async, ldmatrix.
// (round-7 variant; measured 119us on qkv)
// MODE 0: +bias -> fp16 (qkv)     MODE 2: gelu(+bias) -> fp16 (fc1)
// MODE 3: +bias+resid -> fp32 (fc2 -> d_out)
// ---------------------------------------------------------------------------
template <int MODE>
__global__ void __launch_bounds__(256)
hmma_gemm(const __half* __restrict__ A, const __half* __restrict__ Bw,
          const float* __restrict__ bias, const float* __restrict__ resid,
          void* __restrict__ Cout, int N, int K)
{
    extern __shared__ __align__(16) __half sm[];

    const int tid    = threadIdx.x;
    const int warp   = tid >> 5;
    const int lane   = tid & 31;
    const int warp_m = warp & 3;
    const int warp_n = warp >> 2;
    const int bm = blockIdx.y, bn = blockIdx.x;
    const int g = lane >> 2;
    const int t = lane & 3;
    const int la = lane & 7;
    const int a_row_off = ((lane >> 3) & 1) * 8 + la;
    const int a_col_off = (lane >> 4) * 8;
    const int b_grp = lane >> 3;

    float acc[2][6][4];
#pragma unroll
    for (int mt = 0; mt < 2; mt++)
#pragma unroll
        for (int nt = 0; nt < 6; nt++)
#pragma unroll
            for (int e = 0; e < 4; e++) acc[mt][nt][e] = 0.f;

    const int NC = K >> 5;

    auto load_chunk = [&](int c) {
        int s = c % 3;
        __half* a_d = sm + s * 5120;
        __half* b_d = sm + 15360 + s * 3840;
        int k0 = c << 5;
#pragma unroll
        for (int i = tid; i < 512; i += 256) {
            int r = i >> 2, q = i & 3;
            cp_async16(smem_u32(&a_d[r * 40 + q * 8]),
                       A + (size_t)(bm * 128 + r) * K + k0 + q * 8);
        }
        for (int i = tid; i < 384; i += 256) {
            int r = i >> 2, q = i & 3;
            cp_async16(smem_u32(&b_d[r * 40 + q * 8]),
                       Bw + (size_t)(bn * 96 + r) * K + k0 + q * 8);
        }
        cp_commit();
    };

    load_chunk(0);
    load_chunk(1);

    for (int c = 0; c < NC; c++) {
        if (c + 1 < NC) cp_wait1(); else cp_wait0();
        __syncthreads();
        if (c + 2 < NC) load_chunk(c + 2);

        int s = c % 3;
        const __half* a_s = sm + s * 5120;
        const __half* b_s = sm + 15360 + s * 3840;

#pragma unroll
        for (int ksub = 0; ksub < 2; ksub++) {
            const int kb = ksub * 16;
            uint32_t afr[2][4];
#pragma unroll
            for (int mt = 0; mt < 2; mt++)
                ldm_x4(afr[mt], smem_u32(
                    &a_s[(warp_m * 32 + mt * 16 + a_row_off) * 40 + kb + a_col_off]));
#pragma unroll
            for (int p = 0; p < 3; p++) {
                uint32_t br[4];
                ldm_x4(br, smem_u32(
                    &b_s[(warp_n * 48 + (2 * p + (b_grp >> 1)) * 8 + la) * 40
                         + kb + (b_grp & 1) * 8]));
                mma16816(acc[0][2 * p],     afr[0], br[0], br[1]);
                mma16816(acc[1][2 * p],     afr[1], br[0], br[1]);
                mma16816(acc[0][2 * p + 1], afr[0], br[2], br[3]);
                mma16816(acc[1][2 * p + 1], afr[1], br[2], br[3]);
            }
        }
    }

#pragma unroll
    for (int mt = 0; mt < 2; mt++) {
        int row = bm * 128 + warp_m * 32 + mt * 16 + g;
#pragma unroll
        for (int nt = 0; nt < 6; nt++) {
            int col = bn * 96 + warp_n * 48 + nt * 8 + t * 2;
            float b0 = bias[col], b1 = bias[col + 1];
            float v0 = acc[mt][nt][0] + b0;
            float v1 = acc[mt][nt][1] + b1;
            float v2 = acc[mt][nt][2] + b0;
            float v3 = acc[mt][nt][3] + b1;
            if (MODE == 3) {
                float* O = (float*)Cout;
                const float2 rr0 = *(const float2*)(resid + (size_t)row * N + col);
                const float2 rr1 = *(const float2*)(resid + (size_t)(row + 8) * N + col);
                *(float2*)(O + (size_t)row * N + col) = make_float2(v0 + rr0.x, v1 + rr0.y);
                *(float2*)(O + (size_t)(row + 8) * N + col) = make_float2(v2 + rr1.x, v3 + rr1.y);
            } else {
                if (MODE == 2) {
                    v0 = 0.5f * v0 * (1.f + erff(v0 * 0.70710678118654752f));
                    v1 = 0.5f * v1 * (1.f + erff(v1 * 0.70710678118654752f));
                    v2 = 0.5f * v2 * (1.f + erff(v2 * 0.70710678118654752f));
                    v3 = 0.5f * v3 * (1.f + erff(v3 * 0.70710678118654752f));
                }
                __half* O = (__half*)Cout;
                *(__half2*)(O + (size_t)row * N + col)       = __floats2half2_rn(v0, v1);
                *(__half2*)(O + (size_t)(row + 8) * N + col) = __floats2half2_rn(v2, v3);
            }
        }
    }
}

// ---------------------------------------------------------------------------
// gemm_proj: BM=128, BN=192 (full row), BK=32, 3-stage, fused LN2.
// proj: acc+bias+resid[spatial scatter] -> x1 (fp32) AND LN2 -> xn2 (fp16).
// ---------------------------------------------------------------------------
__global__ void __launch_bounds__(256)
gemm_proj(const __half* __restrict__ A, const __half* __restrict__ Bw,
          const float* __restrict__ bias, const float* __restrict__ resid,
          float* __restrict__ Cout, __half* __restrict__ xn2,
          const float* __restrict__ g2, const float* __restrict__ b2)
{
    extern __shared__ __align__(16) __half sm[];
    float2* red = (float2*)(sm + 38400);            // [128][8]
    float2* rowstat = (float2*)(sm + 38400 + 4096); // [128]

    const int tid    = threadIdx.x;
    const int warp   = tid >> 5;
    const int lane   = tid & 31;
    const int warp_m = warp & 3;
    const int warp_n = warp >> 2;
    const int bm = blockIdx.y;
    const int g = lane >> 2;
    const int t = lane & 3;
    const int la = lane & 7;
    const int a_row_off = ((lane >> 3) & 1) * 8 + la;
    const int a_col_off = (lane >> 4) * 8;
    const int b_grp = lane >> 3;
    const int K = C_DIM;

    float acc[2][12][4];
#pragma unroll
    for (int mt = 0; mt < 2; mt++)
#pragma unroll
        for (int nt = 0; nt < 12; nt++)
#pragma unroll
            for (int e = 0; e < 4; e++) acc[mt][nt][e] = 0.f;

    const int NC = K >> 5;

    auto load_chunk = [&](int c) {
        int s = c % 3;
        __half* a_d = sm + s * 5120;
        __half* b_d = sm + 15360 + s * 7680;
        int k0 = c << 5;
#pragma unroll
        for (int i = tid; i < 512; i += 256) {
            int r = i >> 2, q = i & 3;
            cp_async16(smem_u32(&a_d[r * 40 + q * 8]),
                       A + (size_t)(bm * 128 + r) * K + k0 + q * 8);
        }
#pragma unroll
        for (int i = tid; i < 768; i += 256) {
            int r = i >> 2, q = i & 3;
            cp_async16(smem_u32(&b_d[r * 40 + q * 8]),
                       Bw + (size_t)r * K + k0 + q * 8);
        }
        cp_commit();
    };

    load_chunk(0);
    load_chunk(1);

    for (int c = 0; c < NC; c++) {
        if (c + 1 < NC) cp_wait1(); else cp_wait0();
        __syncthreads();
        if (c + 2 < NC) load_chunk(c + 2);

        int s = c % 3;
        const __half* a_s = sm + s * 5120;
        const __half* b_s = sm + 15360 + s * 7680;

#pragma unroll
        for (int ksub = 0; ksub < 2; ksub++) {
            const int kb = ksub * 16;
            uint32_t afr[2][4];
#pragma unroll
            for (int mt = 0; mt < 2; mt++)
                ldm_x4(afr[mt], smem_u32(
                    &a_s[(warp_m * 32 + mt * 16 + a_row_off) * 40 + kb + a_col_off]));
#pragma unroll
            for (int p = 0; p < 6; p++) {
                uint32_t br[4];
                ldm_x4(br, smem_u32(
                    &b_s[(warp_n * 96 + (2 * p + (b_grp >> 1)) * 8 + la) * 40
                         + kb + (b_grp & 1) * 8]));
                mma16816(acc[0][2 * p],     afr[0], br[0], br[1]);
                mma16816(acc[1][2 * p],     afr[1], br[0], br[1]);
                mma16816(acc[0][2 * p + 1], afr[0], br[2], br[3]);
                mma16816(acc[1][2 * p + 1], afr[1], br[2], br[3]);
            }
        }
    }
    __syncthreads();

    int rowL[2][2], orow[2][2];
#pragma unroll
    for (int mt = 0; mt < 2; mt++)
#pragma unroll
        for (int rr = 0; rr < 2; rr++) {
            int rl = warp_m * 32 + mt * 16 + g + rr * 8;
            rowL[mt][rr] = rl;
            int r = bm * 128 + rl;
            int b   = r / (NWIN * NTOK);
            int rem = r % (NWIN * NTOK);
            int w   = rem / NTOK;
            int n   = rem % NTOK;
            int gh  = ((w >> 3) * WSZ + n / WSZ + 3) % 56;
            int gw  = ((w & 7)  * WSZ + n % WSZ + 3) % 56;
            orow[mt][rr] = (b * 56 + gh) * 56 + gw;
        }

#pragma unroll
    for (int mt = 0; mt < 2; mt++) {
        float s0 = 0.f, q0 = 0.f, s1 = 0.f, q1 = 0.f;
#pragma unroll
        for (int nt = 0; nt < 12; nt++) {
            int col = warp_n * 96 + nt * 8 + t * 2;
            float b0 = bias[col], b1 = bias[col + 1];
            const float2 rr0 = *(const float2*)(resid + (size_t)orow[mt][0] * C_DIM + col);
            const float2 rr1 = *(const float2*)(resid + (size_t)orow[mt][1] * C_DIM + col);
            float v0 = acc[mt][nt][0] + b0 + rr0.x;
            float v1 = acc[mt][nt][1] + b1 + rr0.y;
            float v2 = acc[mt][nt][2] + b0 + rr1.x;
            float v3 = acc[mt][nt][3] + b1 + rr1.y;
            acc[mt][nt][0] = v0; acc[mt][nt][1] = v1;
            acc[mt][nt][2] = v2; acc[mt][nt][3] = v3;
            *(float2*)(Cout + (size_t)orow[mt][0] * C_DIM + col) = make_float2(v0, v1);
            *(float2*)(Cout + (size_t)orow[mt][1] * C_DIM + col) = make_float2(v2, v3);
            s0 += v0 + v1; q0 += v0 * v0 + v1 * v1;
            s1 += v2 + v3; q1 += v2 * v2 + v3 * v3;
        }
        red[rowL[mt][0] * 8 + warp_n * 4 + t] = make_float2(s0, q0);
        red[rowL[mt][1] * 8 + warp_n * 4 + t] = make_float2(s1, q1);
    }

    __syncthreads();
    if (tid < 128) {
        float s = 0.f, q = 0.f;
#pragma unroll
        for (int e = 0; e < 8; e++) {
            float2 p = red[tid * 8 + e];
            s += p.x; q += p.y;
        }
        float mu  = s * (1.f / C_DIM);
        float var = q * (1.f / C_DIM) - mu * mu;
        rowstat[tid] = make_float2(mu, rsqrtf(var + 1e-5f));
    }
    __syncthreads();

#pragma unroll
    for (int mt = 0; mt < 2; mt++) {
        float2 st0 = rowstat[rowL[mt][0]];
        float2 st1 = rowstat[rowL[mt][1]];
#pragma unroll
        for (int nt = 0; nt < 12; nt++) {
            int col = warp_n * 96 + nt * 8 + t * 2;
            float gg0 = g2[col], gg1 = g2[col + 1];
            float bb0 = b2[col], bb1 = b2[col + 1];
            float y0 = (acc[mt][nt][0] - st0.x) * st0.y * gg0 + bb0;
            float y1 = (acc[mt][nt][1] - st0.x) * st0.y * gg1 + bb1;
            float y2 = (acc[mt][nt][2] - st1.x) * st1.y * gg0 + bb0;
            float y3 = (acc[mt][nt][3] - st1.x) * st1.y * gg1 + bb1;
            *(__half2*)(xn2 + (size_t)orow[mt][0] * C_DIM + col)
                = __floats2half2_rn(y0, y1);
            *(__half2*)(xn2 + (size_t)orow[mt][1] * C_DIM + col)
                = __floats2half2_rn(y2, y3);
        }
    }
}

// ---------------------------------------------------------------------------
// Launch
// ---------------------------------------------------------------------------
extern "C" void kernel_launch(void* const* d_in, const int* in_sizes, int n_in,
                              void* d_out, int out_size)
{
    const float* x      = (const float*)d_in[0];
    const float* n1g    = (const float*)d_in[1];
    const float* n1b    = (const float*)d_in[2];
    const float* qkv_w  = (const float*)d_in[3];
    const float* qkv_b  = (const float*)d_in[4];
    const float* rpb    = (const float*)d_in[5];
    const float* proj_w = (const float*)d_in[6];
    const float* proj_b = (const float*)d_in[7];
    const float* n2g    = (const float*)d_in[8];
    const float* n2b    = (const float*)d_in[9];
    const float* fc1_w  = (const float*)d_in[10];
    const float* fc1_b  = (const float*)d_in[11];
    const float* fc2_w  = (const float*)d_in[12];
    const float* fc2_b  = (const float*)d_in[13];
    float* out = (float*)d_out;

    __half *xw, *qkvb, *attn, *xn2, *hid, *wqkv, *wproj, *wfc1, *wfc2;
    float  *x1;
    cudaGetSymbolAddress((void**)&xw,    g_xw);
    cudaGetSymbolAddress((void**)&qkvb,  g_qkv);
    cudaGetSymbolAddress((void**)&attn,  g_attn);
    cudaGetSymbolAddress((void**)&x1,    g_x1);
    cudaGetSymbolAddress((void**)&xn2,   g_xn2);
    cudaGetSymbolAddress((void**)&hid,   g_hid);
    cudaGetSymbolAddress((void**)&wqkv,  g_wqkv);
    cudaGetSymbolAddress((void**)&wproj, g_wproj);
    cudaGetSymbolAddress((void**)&wfc1,  g_wfc1);
    cudaGetSymbolAddress((void**)&wfc2,  g_wfc2);

    const int SM_STD = (3 * 5120 + 3 * 3840) * 2;                    // 53760 B
    const int SM_BIG = (3 * 5120 + 3 * 7680) * 2 + 8192 + 1024;      // 86016 B
    cudaFuncSetAttribute(hmma_gemm<0>, cudaFuncAttributeMaxDynamicSharedMemorySize, SM_STD);
    cudaFuncSetAttribute(hmma_gemm<2>, cudaFuncAttributeMaxDynamicSharedMemorySize, SM_STD);
    cudaFuncSetAttribute(hmma_gemm<3>, cudaFuncAttributeMaxDynamicSharedMemorySize, SM_STD);
    cudaFuncSetAttribute(gemm_proj,    cudaFuncAttributeMaxDynamicSharedMemorySize, SM_BIG);

    const int lnBlocks = (T_TOKENS + 7) / 8;

    prep_weights<<<(W_TOTAL + 255) / 256, 256>>>(qkv_w, proj_w, fc1_w, fc2_w);
    prep_bias<<<(4 * NHEADS * 64 * 64 + 255) / 256, 256>>>(rpb);

    // 1. LN1 + shift + window partition
    ln_kernel<<<lnBlocks, 256>>>(x, n1g, n1b, xw);

    // 2. QKV (chunked BN=96)
    hmma_gemm<0><<<dim3(QKV_DIM / 96, MTILES), 256, SM_STD>>>(
        xw, wqkv, qkv_b, nullptr, qkvb, QKV_DIM, C_DIM);

    // 3. Attention
    attn_kernel<<<(T_TOKENS / NTOK) * NHEADS, 128>>>(qkvb, attn);

    // 4. Proj + window reverse + roll + residual -> x1, fused LN2 -> xn2
    gemm_proj<<<dim3(1, MTILES), 256, SM_BIG>>>(
        attn, wproj, proj_b, x, x1, xn2, n2g, n2b);

    // 5. FC1 + exact GELU (chunked BN=96)
    hmma_gemm<2><<<dim3(HID_DIM / 96, MTILES), 256, SM_STD>>>(
        xn2, wfc1, fc1_b, nullptr, hid, HID_DIM, C_DIM);

    // 6. FC2 + residual -> output (chunked BN=96, K=768)
    hmma_gemm<3><<<dim3(C_DIM / 96, MTILES), 256, SM_STD>>>(
        hid, wfc2, fc2_b, x1, out, C_DIM, HID_DIM);
}

// round 12
// speedup vs baseline: 1.2011x; 1.0115x over previous
#include <cuda_runtime.h>
#include <cuda_fp16.h>
#include <math.h>
#include <stdint.h>

// ---------------------------------------------------------------------------
// Swin block: B=32, H=W=56, C=192, NH=6, hd=32, WS=7, SS=3. T=100352 tokens.
// Round 12: attention reworked to one block per (window, head-PAIR) for
// 128B-coalesced qkv loads (2 heads adjacent in memory). GEMM structure
// unchanged from round-11 best (646.6us). Prep kernels merged.
// ---------------------------------------------------------------------------

#define T_TOKENS 100352
#define C_DIM    192
#define HID_DIM  768
#define QKV_DIM  576
#define NHEADS   6
#define HDIM     32
#define WSZ      7
#define NWIN     64
#define NTOK     49
#define MTILES   (T_TOKENS / 128)   // 784

__device__ __half g_xw  [(size_t)T_TOKENS * C_DIM];
__device__ __half g_qkv [(size_t)T_TOKENS * QKV_DIM];
__device__ __half g_attn[(size_t)T_TOKENS * C_DIM];
__device__ float  g_x1  [(size_t)T_TOKENS * C_DIM];
__device__ __half g_xn2 [(size_t)T_TOKENS * C_DIM];
__device__ __half g_hid [(size_t)T_TOKENS * HID_DIM];
__device__ __half g_wqkv [(size_t)QKV_DIM * C_DIM];
__device__ __half g_wproj[(size_t)C_DIM * C_DIM];
__device__ __half g_wfc1 [(size_t)HID_DIM * C_DIM];
__device__ __half g_wfc2 [(size_t)C_DIM * HID_DIM];
// bias+mask table: [class(4)][head(6)][i(64)][j(64)] fp32
__device__ float g_btbl[4 * NHEADS * 64 * 64];

__device__ __forceinline__ uint32_t smem_u32(const void* p) {
    return (uint32_t)__cvta_generic_to_shared(p);
}
__device__ __forceinline__ void cp_async16(uint32_t dst, const void* src) {
    asm volatile("cp.async.cg.shared.global [%0], [%1], 16;" :: "r"(dst), "l"(src));
}
__device__ __forceinline__ void cp_commit() { asm volatile("cp.async.commit_group;"); }
__device__ __forceinline__ void cp_wait1()  { asm volatile("cp.async.wait_group 1;"); }
__device__ __forceinline__ void cp_wait0()  { asm volatile("cp.async.wait_group 0;"); }

__device__ __forceinline__ void mma16816(float* c, const uint32_t* a,
                                         uint32_t b0, uint32_t b1) {
    asm volatile(
        "mma.sync.aligned.m16n8k16.row.col.f32.f16.f16.f32 "
        "{%0,%1,%2,%3}, {%4,%5,%6,%7}, {%8,%9}, {%0,%1,%2,%3};"
        : "+f"(c[0]), "+f"(c[1]), "+f"(c[2]), "+f"(c[3])
        : "r"(a[0]), "r"(a[1]), "r"(a[2]), "r"(a[3]), "r"(b0), "r"(b1));
}
__device__ __forceinline__ void ldm_x4(uint32_t* r, uint32_t addr) {
    asm volatile("ldmatrix.sync.aligned.m8n8.x4.shared.b16 {%0,%1,%2,%3}, [%4];"
        : "=r"(r[0]), "=r"(r[1]), "=r"(r[2]), "=r"(r[3]) : "r"(addr));
}

// ---------------------------------------------------------------------------
// Merged prep: weight transpose/convert + bias+mask table, one launch.
// ---------------------------------------------------------------------------
#define W_QKV_E (QKV_DIM * C_DIM)
#define W_PRJ_E (C_DIM * C_DIM)
#define W_FC1_E (HID_DIM * C_DIM)
#define W_FC2_E (C_DIM * HID_DIM)
#define W_TOTAL (W_QKV_E + W_PRJ_E + W_FC1_E + W_FC2_E)
#define BT_TOTAL (4 * NHEADS * 64 * 64)

__global__ void prep_all(const float* __restrict__ qkv_w,
                         const float* __restrict__ proj_w,
                         const float* __restrict__ fc1_w,
                         const float* __restrict__ fc2_w,
                         const float* __restrict__ rpb)
{
    int i = blockIdx.x * blockDim.x + threadIdx.x;
    if (i < W_TOTAL) {
        if (i < W_QKV_E) {
            int n = i / C_DIM, k = i % C_DIM;
            g_wqkv[i] = __float2half(qkv_w[k * QKV_DIM + n]);
        } else if (i < W_QKV_E + W_PRJ_E) {
            int j = i - W_QKV_E;
            int n = j / C_DIM, k = j % C_DIM;
            g_wproj[j] = __float2half(proj_w[k * C_DIM + n]);
        } else if (i < W_QKV_E + W_PRJ_E + W_FC1_E) {
            int j = i - W_QKV_E - W_PRJ_E;
            int n = j / C_DIM, k = j % C_DIM;
            g_wfc1[j] = __float2half(fc1_w[k * HID_DIM + n]);
        } else {
            int j = i - W_QKV_E - W_PRJ_E - W_FC1_E;
            int n = j / HID_DIM, k = j % HID_DIM;
            g_wfc2[j] = __float2half(fc2_w[k * C_DIM + n]);
        }
        return;
    }
    int idx = i - W_TOTAL;
    if (idx >= BT_TOTAL) return;
    int j = idx & 63, ii = (idx >> 6) & 63;
    int h = (idx >> 12) % NHEADS;
    int cls = idx / (64 * 64 * NHEADS);
    float v;
    if (ii >= NTOK || j >= NTOK) {
        v = -1e30f;
    } else {
        int fh = cls >> 1, fw = cls & 1;
        int ri = ii / WSZ, ci = ii % WSZ, rj = j / WSZ, cj = j % WSZ;
        int rgI = (fh ? (ri < 4 ? 1 : 2) : 0) * 3 + (fw ? (ci < 4 ? 1 : 2) : 0);
        int rgJ = (fh ? (rj < 4 ? 1 : 2) : 0) * 3 + (fw ? (cj < 4 ? 1 : 2) : 0);
        v = rpb[((ri - rj + 6) * 13 + (ci - cj + 6)) * NHEADS + h]
          + ((rgI != rgJ) ? -100.f : 0.f);
    }
    g_btbl[idx] = v;
}

// ---------------------------------------------------------------------------
// LayerNorm (warp per row), shifted-window gather, fp16 out. (LN1 only)
// ---------------------------------------------------------------------------
__global__ void ln_kernel(const float* __restrict__ x,
                          const float* __restrict__ gamma,
                          const float* __restrict__ beta,
                          __half* __restrict__ out)
{
    int warp = (blockIdx.x * blockDim.x + threadIdx.x) >> 5;
    int lane = threadIdx.x & 31;
    if (warp >= T_TOKENS) return;

    int b   = warp / (NWIN * NTOK);
    int rem = warp % (NWIN * NTOK);
    int w   = rem / NTOK;
    int n   = rem % NTOK;
    int gh  = ((w >> 3) * WSZ + n / WSZ + 3) % 56;
    int gw  = ((w & 7)  * WSZ + n % WSZ + 3) % 56;
    int src = (b * 56 + gh) * 56 + gw;
    const float* row = x + (size_t)src * C_DIM;

    float v[6], s = 0.f, sq = 0.f;
#pragma unroll
    for (int k = 0; k < 6; k++) {
        v[k] = row[lane + 32 * k];
        s += v[k]; sq += v[k] * v[k];
    }
#pragma unroll
    for (int o = 16; o; o >>= 1) {
        s  += __shfl_xor_sync(0xffffffffu, s,  o);
        sq += __shfl_xor_sync(0xffffffffu, sq, o);
    }
    float mu  = s * (1.f / C_DIM);
    float var = sq * (1.f / C_DIM) - mu * mu;
    float inv = rsqrtf(var + 1e-5f);

    __half* orow = out + (size_t)warp * C_DIM;
#pragma unroll
    for (int k = 0; k < 6; k++) {
        int c = lane + 32 * k;
        orow[c] = __float2half((v[k] - mu) * inv * gamma[c] + beta[c]);
    }
}

// ---------------------------------------------------------------------------
// HMMA windowed attention: one block per (window, head-PAIR). 256 threads,
// warps 0-3 -> head 2p, warps 4-7 -> head 2p+1 (own smem slab each).
// qkv loads are 128B-contiguous (both heads' 64 halves fetched uint4-wide).
// ---------------------------------------------------------------------------
#define QK_STR  40
#define PV_STR  72

__global__ void __launch_bounds__(256)
attn_kernel(const __half* __restrict__ qkv, __half* __restrict__ out)
{
    __shared__ __align__(16) __half qs[2][64 * QK_STR];
    __shared__ __align__(16) __half ks[2][64 * QK_STR];
    __shared__ __align__(16) __half vT[2][32 * PV_STR];
    __shared__ __align__(16) __half ps[2][64 * PV_STR];

    const int bw   = blockIdx.x / (NHEADS / 2);
    const int hp   = blockIdx.x % (NHEADS / 2);
    const int h0   = hp * 2;
    const int w    = bw % NWIN;
    const int base = bw * NTOK;
    const int tid  = threadIdx.x;
    const int warp = tid >> 5;
    const int hh   = warp >> 2;        // head within pair (0/1)
    const int wl   = warp & 3;         // warp within head
    const int lane = tid & 31;
    const int g    = lane >> 2;
    const int t    = lane & 3;
    const int mrow = wl * 16;

    // zero all slabs (pad rows/cols must be 0)
    {
        uint4 z = make_uint4(0, 0, 0, 0);
        uint4* p0 = (uint4*)qs;
        for (int i = tid; i < 2 * 64 * QK_STR / 8; i += 256) p0[i] = z;
        uint4* p1 = (uint4*)ks;
        for (int i = tid; i < 2 * 64 * QK_STR / 8; i += 256) p1[i] = z;
        uint4* p2 = (uint4*)vT;
        for (int i = tid; i < 2 * 32 * PV_STR / 8; i += 256) p2[i] = z;
    }
    __syncthreads();

    // load q,k (row-major) and v transposed; 8 threads cover 128B per row
    for (int idx = tid; idx < NTOK * 8; idx += 256) {
        int i = idx >> 3, seg = idx & 7;
        int hd = seg >> 2;             // which head of the pair
        int d  = (seg & 3) * 8;        // dim offset within head
        const __half* r = qkv + (size_t)(base + i) * QKV_DIM + h0 * HDIM + seg * 8;
        *(uint4*)&qs[hd][i * QK_STR + d] = *(const uint4*)(r);
        *(uint4*)&ks[hd][i * QK_STR + d] = *(const uint4*)(r + C_DIM);
        __half vv[8];
        *(uint4*)vv = *(const uint4*)(r + 2 * C_DIM);
#pragma unroll
        for (int jj = 0; jj < 8; jj++)
            vT[hd][(d + jj) * PV_STR + i] = vv[jj];
    }
    __syncthreads();

    // ---- S = Q @ K^T ------------------------------------------------------
    float c[8][4];
#pragma unroll
    for (int nt = 0; nt < 8; nt++)
#pragma unroll
        for (int e = 0; e < 4; e++) c[nt][e] = 0.f;

#pragma unroll
    for (int kst = 0; kst < 2; kst++) {
        const int kb = kst * 16 + t * 2;
        uint32_t a[4];
        a[0] = *(const uint32_t*)&qs[hh][(mrow + g)     * QK_STR + kb];
        a[1] = *(const uint32_t*)&qs[hh][(mrow + g + 8) * QK_STR + kb];
        a[2] = *(const uint32_t*)&qs[hh][(mrow + g)     * QK_STR + kb + 8];
        a[3] = *(const uint32_t*)&qs[hh][(mrow + g + 8) * QK_STR + kb + 8];
#pragma unroll
        for (int nt = 0; nt < 8; nt++) {
            uint32_t b0 = *(const uint32_t*)&ks[hh][(nt * 8 + g) * QK_STR + kb];
            uint32_t b1 = *(const uint32_t*)&ks[hh][(nt * 8 + g) * QK_STR + kb + 8];
            mma16816(c[nt], a, b0, b1);
        }
    }

    // ---- scale + table bias ----------------------------------------------
    const int wh = w >> 3, ww = w & 7;
    const int cls = ((wh == 7) ? 2 : 0) + ((ww == 7) ? 1 : 0);
    const float* tb = g_btbl + (size_t)(cls * NHEADS + h0 + hh) * 4096;
    const int i0 = mrow + g, i1 = mrow + g + 8;
    const float scale = 0.17677669529663687f;

#pragma unroll
    for (int nt = 0; nt < 8; nt++) {
        int jc = nt * 8 + t * 2;
        float2 t0 = *(const float2*)&tb[i0 * 64 + jc];
        float2 t1 = *(const float2*)&tb[i1 * 64 + jc];
        c[nt][0] = fmaf(c[nt][0], scale, t0.x);
        c[nt][1] = fmaf(c[nt][1], scale, t0.y);
        c[nt][2] = fmaf(c[nt][2], scale, t1.x);
        c[nt][3] = fmaf(c[nt][3], scale, t1.y);
    }

    // ---- softmax in register fragments -----------------------------------
    float m0 = -1e30f, m1 = -1e30f;
#pragma unroll
    for (int nt = 0; nt < 8; nt++) {
        m0 = fmaxf(m0, fmaxf(c[nt][0], c[nt][1]));
        m1 = fmaxf(m1, fmaxf(c[nt][2], c[nt][3]));
    }
    m0 = fmaxf(m0, __shfl_xor_sync(0xffffffffu, m0, 1));
    m0 = fmaxf(m0, __shfl_xor_sync(0xffffffffu, m0, 2));
    m1 = fmaxf(m1, __shfl_xor_sync(0xffffffffu, m1, 1));
    m1 = fmaxf(m1, __shfl_xor_sync(0xffffffffu, m1, 2));

    float s0 = 0.f, s1 = 0.f;
#pragma unroll
    for (int nt = 0; nt < 8; nt++) {
        c[nt][0] = expf(c[nt][0] - m0);
        c[nt][1] = expf(c[nt][1] - m0);
        c[nt][2] = expf(c[nt][2] - m1);
        c[nt][3] = expf(c[nt][3] - m1);
        s0 += c[nt][0] + c[nt][1];
        s1 += c[nt][2] + c[nt][3];
    }
    s0 += __shfl_xor_sync(0xffffffffu, s0, 1);
    s0 += __shfl_xor_sync(0xffffffffu, s0, 2);
    s1 += __shfl_xor_sync(0xffffffffu, s1, 1);
    s1 += __shfl_xor_sync(0xffffffffu, s1, 2);
    const float r0 = 1.f / s0, r1 = 1.f / s1;

#pragma unroll
    for (int nt = 0; nt < 8; nt++) {
        int jcol = nt * 8 + t * 2;
        *(__half2*)&ps[hh][i0 * PV_STR + jcol] = __floats2half2_rn(c[nt][0] * r0, c[nt][1] * r0);
        *(__half2*)&ps[hh][i1 * PV_STR + jcol] = __floats2half2_rn(c[nt][2] * r1, c[nt][3] * r1);
    }
    __syncthreads();

    // ---- O = P @ V --------------------------------------------------------
    float o[4][4];
#pragma unroll
    for (int nt = 0; nt < 4; nt++)
#pragma unroll
        for (int e = 0; e < 4; e++) o[nt][e] = 0.f;

#pragma unroll
    for (int kst = 0; kst < 4; kst++) {
        const int kb = kst * 16 + t * 2;
        uint32_t a[4];
        a[0] = *(const uint32_t*)&ps[hh][(mrow + g)     * PV_STR + kb];
        a[1] = *(const uint32_t*)&ps[hh][(mrow + g + 8) * PV_STR + kb];
        a[2] = *(const uint32_t*)&ps[hh][(mrow + g)     * PV_STR + kb + 8];
        a[3] = *(const uint32_t*)&ps[hh][(mrow + g + 8) * PV_STR + kb + 8];
#pragma unroll
        for (int nt = 0; nt < 4; nt++) {
            uint32_t b0 = *(const uint32_t*)&vT[hh][(nt * 8 + g) * PV_STR + kb];
            uint32_t b1 = *(const uint32_t*)&vT[hh][(nt * 8 + g) * PV_STR + kb + 8];
            mma16816(o[nt], a, b0, b1);
        }
    }

#pragma unroll
    for (int nt = 0; nt < 4; nt++) {
        int d = nt * 8 + t * 2;
        if (i0 < NTOK)
            *(__half2*)(out + (size_t)(base + i0) * C_DIM + (h0 + hh) * HDIM + d)
                = __floats2half2_rn(o[nt][0], o[nt][1]);
        if (i1 < NTOK)
            *(__half2*)(out + (size_t)(base + i1) * C_DIM + (h0 + hh) * HDIM + d)
                = __floats2half2_rn(o[nt][2], o[nt][3]);
    }
}

// ---------------------------------------------------------------------------
// Chunked HMMA GEMM: BM=128, BN=96, BK=32, 3-stage cp.async, ldmatrix.
// MODE 0: +bias -> fp16 (qkv)     MODE 2: gelu(+bias) -> fp16 (fc1)
// MODE 3: +bias+resid -> fp32 (fc2 -> d_out)
// ---------------------------------------------------------------------------
template <int MODE>
__global__ void __launch_bounds__(256)
hmma_gemm(const __half* __restrict__ A, const __half* __restrict__ Bw,
          const float* __restrict__ bias, const float* __restrict__ resid,
          void* __restrict__ Cout, int N, int K)
{
    extern __shared__ __align__(16) __half sm[];

    const int tid    = threadIdx.x;
    const int warp   = tid >> 5;
    const int lane   = tid & 31;
    const int warp_m = warp & 3;
    const int warp_n = warp >> 2;
    const int bm = blockIdx.y, bn = blockIdx.x;
    const int g = lane >> 2;
    const int t = lane & 3;
    const int la = lane & 7;
    const int a_row_off = ((lane >> 3) & 1) * 8 + la;
    const int a_col_off = (lane >> 4) * 8;
    const int b_grp = lane >> 3;

    float acc[2][6][4];
#pragma unroll
    for (int mt = 0; mt < 2; mt++)
#pragma unroll
        for (int nt = 0; nt < 6; nt++)
#pragma unroll
            for (int e = 0; e < 4; e++) acc[mt][nt][e] = 0.f;

    const int NC = K >> 5;

    auto load_chunk = [&](int c) {
        int s = c % 3;
        __half* a_d = sm + s * 5120;
        __half* b_d = sm + 15360 + s * 3840;
        int k0 = c << 5;
#pragma unroll
        for (int i = tid; i < 512; i += 256) {
            int r = i >> 2, q = i & 3;
            cp_async16(smem_u32(&a_d[r * 40 + q * 8]),
                       A + (size_t)(bm * 128 + r) * K + k0 + q * 8);
        }
        for (int i = tid; i < 384; i += 256) {
            int r = i >> 2, q = i & 3;
            cp_async16(smem_u32(&b_d[r * 40 + q * 8]),
                       Bw + (size_t)(bn * 96 + r) * K + k0 + q * 8);
        }
        cp_commit();
    };

    load_chunk(0);
    load_chunk(1);

    for (int c = 0; c < NC; c++) {
        if (c + 1 < NC) cp_wait1(); else cp_wait0();
        __syncthreads();
        if (c + 2 < NC) load_chunk(c + 2);

        int s = c % 3;
        const __half* a_s = sm + s * 5120;
        const __half* b_s = sm + 15360 + s * 3840;

#pragma unroll
        for (int ksub = 0; ksub < 2; ksub++) {
            const int kb = ksub * 16;
            uint32_t afr[2][4];
#pragma unroll
            for (int mt = 0; mt < 2; mt++)
                ldm_x4(afr[mt], smem_u32(
                    &a_s[(warp_m * 32 + mt * 16 + a_row_off) * 40 + kb + a_col_off]));
#pragma unroll
            for (int p = 0; p < 3; p++) {
                uint32_t br[4];
                ldm_x4(br, smem_u32(
                    &b_s[(warp_n * 48 + (2 * p + (b_grp >> 1)) * 8 + la) * 40
                         + kb + (b_grp & 1) * 8]));
                mma16816(acc[0][2 * p],     afr[0], br[0], br[1]);
                mma16816(acc[1][2 * p],     afr[1], br[0], br[1]);
                mma16816(acc[0][2 * p + 1], afr[0], br[2], br[3]);
                mma16816(acc[1][2 * p + 1], afr[1], br[2], br[3]);
            }
        }
    }

#pragma unroll
    for (int mt = 0; mt < 2; mt++) {
        int row = bm * 128 + warp_m * 32 + mt * 16 + g;
#pragma unroll
        for (int nt = 0; nt < 6; nt++) {
            int col = bn * 96 + warp_n * 48 + nt * 8 + t * 2;
            float b0 = bias[col], b1 = bias[col + 1];
            float v0 = acc[mt][nt][0] + b0;
            float v1 = acc[mt][nt][1] + b1;
            float v2 = acc[mt][nt][2] + b0;
            float v3 = acc[mt][nt][3] + b1;
            if (MODE == 3) {
                float* O = (float*)Cout;
                const float2 rr0 = *(const float2*)(resid + (size_t)row * N + col);
                const float2 rr1 = *(const float2*)(resid + (size_t)(row + 8) * N + col);
                *(float2*)(O + (size_t)row * N + col) = make_float2(v0 + rr0.x, v1 + rr0.y);
                *(float2*)(O + (size_t)(row + 8) * N + col) = make_float2(v2 + rr1.x, v3 + rr1.y);
            } else {
                if (MODE == 2) {
                    v0 = 0.5f * v0 * (1.f + erff(v0 * 0.70710678118654752f));
                    v1 = 0.5f * v1 * (1.f + erff(v1 * 0.70710678118654752f));
                    v2 = 0.5f * v2 * (1.f + erff(v2 * 0.70710678118654752f));
                    v3 = 0.5f * v3 * (1.f + erff(v3 * 0.70710678118654752f));
                }
                __half* O = (__half*)Cout;
                *(__half2*)(O + (size_t)row * N + col)       = __floats2half2_rn(v0, v1);
                *(__half2*)(O + (size_t)(row + 8) * N + col) = __floats2half2_rn(v2, v3);
            }
        }
    }
}

// ---------------------------------------------------------------------------
// gemm_proj: BM=128, BN=192 (full row), BK=32, 3-stage, fused LN2.
// ---------------------------------------------------------------------------
__global__ void __launch_bounds__(256)
gemm_proj(const __half* __restrict__ A, const __half* __restrict__ Bw,
          const float* __restrict__ bias, const float* __restrict__ resid,
          float* __restrict__ Cout, __half* __restrict__ xn2,
          const float* __restrict__ g2, const float* __restrict__ b2)
{
    extern __shared__ __align__(16) __half sm[];
    float2* red = (float2*)(sm + 38400);            // [128][8]
    float2* rowstat = (float2*)(sm + 38400 + 4096); // [128]

    const int tid    = threadIdx.x;
    const int warp   = tid >> 5;
    const int lane   = tid & 31;
    const int warp_m = warp & 3;
    const int warp_n = warp >> 2;
    const int bm = blockIdx.y;
    const int g = lane >> 2;
    const int t = lane & 3;
    const int la = lane & 7;
    const int a_row_off = ((lane >> 3) & 1) * 8 + la;
    const int a_col_off = (lane >> 4) * 8;
    const int b_grp = lane >> 3;
    const int K = C_DIM;

    float acc[2][12][4];
#pragma unroll
    for (int mt = 0; mt < 2; mt++)
#pragma unroll
        for (int nt = 0; nt < 12; nt++)
#pragma unroll
            for (int e = 0; e < 4; e++) acc[mt][nt][e] = 0.f;

    const int NC = K >> 5;

    auto load_chunk = [&](int c) {
        int s = c % 3;
        __half* a_d = sm + s * 5120;
        __half* b_d = sm + 15360 + s * 7680;
        int k0 = c << 5;
#pragma unroll
        for (int i = tid; i < 512; i += 256) {
            int r = i >> 2, q = i & 3;
            cp_async16(smem_u32(&a_d[r * 40 + q * 8]),
                       A + (size_t)(bm * 128 + r) * K + k0 + q * 8);
        }
#pragma unroll
        for (int i = tid; i < 768; i += 256) {
            int r = i >> 2, q = i & 3;
            cp_async16(smem_u32(&b_d[r * 40 + q * 8]),
                       Bw + (size_t)r * K + k0 + q * 8);
        }
        cp_commit();
    };

    load_chunk(0);
    load_chunk(1);

    for (int c = 0; c < NC; c++) {
        if (c + 1 < NC) cp_wait1(); else cp_wait0();
        __syncthreads();
        if (c + 2 < NC) load_chunk(c + 2);

        int s = c % 3;
        const __half* a_s = sm + s * 5120;
        const __half* b_s = sm + 15360 + s * 7680;

#pragma unroll
        for (int ksub = 0; ksub < 2; ksub++) {
            const int kb = ksub * 16;
            uint32_t afr[2][4];
#pragma unroll
            for (int mt = 0; mt < 2; mt++)
                ldm_x4(afr[mt], smem_u32(
                    &a_s[(warp_m * 32 + mt * 16 + a_row_off) * 40 + kb + a_col_off]));
#pragma unroll
            for (int p = 0; p < 6; p++) {
                uint32_t br[4];
                ldm_x4(br, smem_u32(
                    &b_s[(warp_n * 96 + (2 * p + (b_grp >> 1)) * 8 + la) * 40
                         + kb + (b_grp & 1) * 8]));
                mma16816(acc[0][2 * p],     afr[0], br[0], br[1]);
                mma16816(acc[1][2 * p],     afr[1], br[0], br[1]);
                mma16816(acc[0][2 * p + 1], afr[0], br[2], br[3]);
                mma16816(acc[1][2 * p + 1], afr[1], br[2], br[3]);
            }
        }
    }
    __syncthreads();

    int rowL[2][2], orow[2][2];
#pragma unroll
    for (int mt = 0; mt < 2; mt++)
#pragma unroll
        for (int rr = 0; rr < 2; rr++) {
            int rl = warp_m * 32 + mt * 16 + g + rr * 8;
            rowL[mt][rr] = rl;
            int r = bm * 128 + rl;
            int b   = r / (NWIN * NTOK);
            int rem = r % (NWIN * NTOK);
            int w   = rem / NTOK;
            int n   = rem % NTOK;
            int gh  = ((w >> 3) * WSZ + n / WSZ + 3) % 56;
            int gw  = ((w & 7)  * WSZ + n % WSZ + 3) % 56;
            orow[mt][rr] = (b * 56 + gh) * 56 + gw;
        }

#pragma unroll
    for (int mt = 0; mt < 2; mt++) {
        float s0 = 0.f, q0 = 0.f, s1 = 0.f, q1 = 0.f;
#pragma unroll
        for (int nt = 0; nt < 12; nt++) {
            int col = warp_n * 96 + nt * 8 + t * 2;
            float b0 = bias[col], b1 = bias[col + 1];
            const float2 rr0 = *(const float2*)(resid + (size_t)orow[mt][0] * C_DIM + col);
            const float2 rr1 = *(const float2*)(resid + (size_t)orow[mt][1] * C_DIM + col);
            float v0 = acc[mt][nt][0] + b0 + rr0.x;
            float v1 = acc[mt][nt][1] + b1 + rr0.y;
            float v2 = acc[mt][nt][2] + b0 + rr1.x;
            float v3 = acc[mt][nt][3] + b1 + rr1.y;
            acc[mt][nt][0] = v0; acc[mt][nt][1] = v1;
            acc[mt][nt][2] = v2; acc[mt][nt][3] = v3;
            *(float2*)(Cout + (size_t)orow[mt][0] * C_DIM + col) = make_float2(v0, v1);
            *(float2*)(Cout + (size_t)orow[mt][1] * C_DIM + col) = make_float2(v2, v3);
            s0 += v0 + v1; q0 += v0 * v0 + v1 * v1;
            s1 += v2 + v3; q1 += v2 * v2 + v3 * v3;
        }
        red[rowL[mt][0] * 8 + warp_n * 4 + t] = make_float2(s0, q0);
        red[rowL[mt][1] * 8 + warp_n * 4 + t] = make_float2(s1, q1);
    }

    __syncthreads();
    if (tid < 128) {
        float s = 0.f, q = 0.f;
#pragma unroll
        for (int e = 0; e < 8; e++) {
            float2 p = red[tid * 8 + e];
            s += p.x; q += p.y;
        }
        float mu  = s * (1.f / C_DIM);
        float var = q * (1.f / C_DIM) - mu * mu;
        rowstat[tid] = make_float2(mu, rsqrtf(var + 1e-5f));
    }
    __syncthreads();

#pragma unroll
    for (int mt = 0; mt < 2; mt++) {
        float2 st0 = rowstat[rowL[mt][0]];
        float2 st1 = rowstat[rowL[mt][1]];
#pragma unroll
        for (int nt = 0; nt < 12; nt++) {
            int col = warp_n * 96 + nt * 8 + t * 2;
            float gg0 = g2[col], gg1 = g2[col + 1];
            float bb0 = b2[col], bb1 = b2[col + 1];
            float y0 = (acc[mt][nt][0] - st0.x) * st0.y * gg0 + bb0;
            float y1 = (acc[mt][nt][1] - st0.x) * st0.y * gg1 + bb1;
            float y2 = (acc[mt][nt][2] - st1.x) * st1.y * gg0 + bb0;
            float y3 = (acc[mt][nt][3] - st1.x) * st1.y * gg1 + bb1;
            *(__half2*)(xn2 + (size_t)orow[mt][0] * C_DIM + col)
                = __floats2half2_rn(y0, y1);
            *(__half2*)(xn2 + (size_t)orow[mt][1] * C_DIM + col)
                = __floats2half2_rn(y2, y3);
        }
    }
}

// ---------------------------------------------------------------------------
// Launch
// ---------------------------------------------------------------------------
extern "C" void kernel_launch(void* const* d_in, const int* in_sizes, int n_in,
                              void* d_out, int out_size)
{
    const float* x      = (const float*)d_in[0];
    const float* n1g    = (const float*)d_in[1];
    const float* n1b    = (const float*)d_in[2];
    const float* qkv_w  = (const float*)d_in[3];
    const float* qkv_b  = (const float*)d_in[4];
    const float* rpb    = (const float*)d_in[5];
    const float* proj_w = (const float*)d_in[6];
    const float* proj_b = (const float*)d_in[7];
    const float* n2g    = (const float*)d_in[8];
    const float* n2b    = (const float*)d_in[9];
    const float* fc1_w  = (const float*)d_in[10];
    const float* fc1_b  = (const float*)d_in[11];
    const float* fc2_w  = (const float*)d_in[12];
    const float* fc2_b  = (const float*)d_in[13];
    float* out = (float*)d_out;

    __half *xw, *qkvb, *attn, *xn2, *hid, *wqkv, *wproj, *wfc1, *wfc2;
    float  *x1;
    cudaGetSymbolAddress((void**)&xw,    g_xw);
    cudaGetSymbolAddress((void**)&qkvb,  g_qkv);
    cudaGetSymbolAddress((void**)&attn,  g_attn);
    cudaGetSymbolAddress((void**)&x1,    g_x1);
    cudaGetSymbolAddress((void**)&xn2,   g_xn2);
    cudaGetSymbolAddress((void**)&hid,   g_hid);
    cudaGetSymbolAddress((void**)&wqkv,  g_wqkv);
    cudaGetSymbolAddress((void**)&wproj, g_wproj);
    cudaGetSymbolAddress((void**)&wfc1,  g_wfc1);
    cudaGetSymbolAddress((void**)&wfc2,  g_wfc2);

    const int SM_STD = (3 * 5120 + 3 * 3840) * 2;                    // 53760 B
    const int SM_BIG = (3 * 5120 + 3 * 7680) * 2 + 8192 + 1024;      // 86016 B
    cudaFuncSetAttribute(hmma_gemm<0>, cudaFuncAttributeMaxDynamicSharedMemorySize, SM_STD);
    cudaFuncSetAttribute(hmma_gemm<2>, cudaFuncAttributeMaxDynamicSharedMemorySize, SM_STD);
    cudaFuncSetAttribute(hmma_gemm<3>, cudaFuncAttributeMaxDynamicSharedMemorySize, SM_STD);
    cudaFuncSetAttribute(gemm_proj,    cudaFuncAttributeMaxDynamicSharedMemorySize, SM_BIG);

    const int lnBlocks = (T_TOKENS + 7) / 8;

    // 0. merged prep (weights + bias table)
    prep_all<<<(W_TOTAL + BT_TOTAL + 255) / 256, 256>>>(
        qkv_w, proj_w, fc1_w, fc2_w, rpb);

    // 1. LN1 + shift + window partition
    ln_kernel<<<lnBlocks, 256>>>(x, n1g, n1b, xw);

    // 2. QKV (chunked BN=96)
    hmma_gemm<0><<<dim3(QKV_DIM / 96, MTILES), 256, SM_STD>>>(
        xw, wqkv, qkv_b, nullptr, qkvb, QKV_DIM, C_DIM);

    // 3. Attention: one block per (window, head-pair)
    attn_kernel<<<(T_TOKENS / NTOK) * (NHEADS / 2), 256>>>(qkvb, attn);

    // 4. Proj + window reverse + roll + residual -> x1, fused LN2 -> xn2
    gemm_proj<<<dim3(1, MTILES), 256, SM_BIG>>>(
        attn, wproj, proj_b, x, x1, xn2, n2g, n2b);

    // 5. FC1 + exact GELU (chunked BN=96)
    hmma_gemm<2><<<dim3(HID_DIM / 96, MTILES), 256, SM_STD>>>(
        xn2, wfc1, fc1_b, nullptr, hid, HID_DIM, C_DIM);

    // 6. FC2 + residual -> output (chunked BN=96, K=768)
    hmma_gemm<3><<<dim3(C_DIM / 96, MTILES), 256, SM_STD>>>(
        hid, wfc2, fc2_b, x1, out, C_DIM, HID_DIM);
}